// round 13
// baseline (speedup 1.0000x reference)
#include <cuda_runtime.h>
#include <cuda_fp16.h>
#include <math.h>
#include <stdint.h>

// ---------------------------------------------------------------------------
// HawkBlock: fp16 mma.sync GEMMs, f32 accum, 3-stage mbarrier ring.
// Dual-B fusions: (w_in + w_gate) and (mlp gate + up -> silu fused).
// Fast-math epilogues, f16 'a' + f16 xres, recompute-style parallel scan.
// ---------------------------------------------------------------------------

#define NTOK   16384
#define HIDDEN 1024
#define DREC   2048
#define INTER  4096
#define TLEN   4096
#define NB     4

#define SCHUNK   64
#define NCHUNKS  (TLEN / SCHUNK)   // 64
#define NCHAN    (NB * DREC)       // 8192

typedef __half f16;

// ---- static scratch ----
__device__ f16   g_h   [(size_t)NTOK * HIDDEN];
__device__ f16   g_h2  [(size_t)NTOK * HIDDEN];
__device__ f16   g_xres[(size_t)NTOK * HIDDEN];
__device__ f16   g_xin [(size_t)NTOK * DREC];
__device__ f16   g_gate[(size_t)NTOK * DREC];
__device__ f16   g_a   [(size_t)NTOK * DREC];
__device__ f16   g_y   [(size_t)NTOK * DREC];
__device__ f16   g_mu  [(size_t)NTOK * INTER];
__device__ float g_csum [2 * NCHUNKS * NCHAN];
__device__ float g_carry[NCHUNKS * NCHAN];

// ---- fp16 weights ----
__device__ f16 g_wi [(size_t)DREC * HIDDEN];
__device__ f16 g_wg [(size_t)DREC * HIDDEN];
__device__ f16 g_wa [(size_t)DREC * DREC];
__device__ f16 g_wo [(size_t)HIDDEN * DREC];
__device__ f16 g_wmg[(size_t)INTER * HIDDEN];
__device__ f16 g_wmu[(size_t)INTER * HIDDEN];
__device__ f16 g_wmd[(size_t)HIDDEN * INTER];

// ---------------------------------------------------------------------------
// helpers
// ---------------------------------------------------------------------------
__device__ __forceinline__ uint32_t smem_u32(const void* p) {
    uint32_t a;
    asm("{ .reg .u64 t; cvta.to.shared.u64 t, %1; cvt.u32.u64 %0, t; }"
        : "=r"(a) : "l"(p));
    return a;
}
__device__ __forceinline__ void cp16(uint32_t dst, const void* src) {
    asm volatile("cp.async.cg.shared.global [%0], [%1], 16;"
                 :: "r"(dst), "l"(src));
}
__device__ __forceinline__ void ldsm4(uint32_t (&r)[4], uint32_t addr) {
    asm volatile("ldmatrix.sync.aligned.m8n8.x4.shared.b16 {%0,%1,%2,%3}, [%4];"
                 : "=r"(r[0]), "=r"(r[1]), "=r"(r[2]), "=r"(r[3]) : "r"(addr));
}
__device__ __forceinline__ void mma_f16(float (&d)[4], const uint32_t (&a)[4],
                                        uint32_t b0, uint32_t b1) {
    asm volatile("mma.sync.aligned.m16n8k16.row.col.f32.f16.f16.f32 "
                 "{%0,%1,%2,%3}, {%4,%5,%6,%7}, {%8,%9}, {%0,%1,%2,%3};"
                 : "+f"(d[0]), "+f"(d[1]), "+f"(d[2]), "+f"(d[3])
                 : "r"(a[0]), "r"(a[1]), "r"(a[2]), "r"(a[3]), "r"(b0), "r"(b1));
}
__device__ __forceinline__ uint32_t pack_h2(f16 a, f16 b) {
    __half2 t = __halves2half2(a, b);
    return *reinterpret_cast<uint32_t*>(&t);
}
__device__ __forceinline__ float fast_sig(float v) {
    return __fdividef(1.0f, 1.0f + __expf(-v));
}

// ---- mbarrier primitives ----
#define MBAR_INIT(addr, cnt) \
    asm volatile("mbarrier.init.shared.b64 [%0], %1;" \
                 :: "r"((uint32_t)(addr)), "r"((uint32_t)(cnt)) : "memory")
#define MBAR_ARRIVE(addr) \
    asm volatile("mbarrier.arrive.shared.b64 _, [%0];" \
                 :: "r"((uint32_t)(addr)) : "memory")
#define CP_MBAR_ARRIVE(addr) \
    asm volatile("cp.async.mbarrier.arrive.noinc.shared.b64 [%0];" \
                 :: "r"((uint32_t)(addr)) : "memory")
#define MBAR_WAIT(addr, parity) do {                                            \
    uint32_t _m = (uint32_t)(addr); uint32_t _p = (uint32_t)(parity);           \
    uint32_t _d;                                                                \
    asm volatile("{\n\t.reg .pred p;\n\t"                                       \
        "mbarrier.try_wait.parity.acquire.cta.shared::cta.b64 p, [%1], %2;\n\t" \
        "selp.b32 %0, 1, 0, p;\n\t}" : "=r"(_d) : "r"(_m), "r"(_p) : "memory"); \
    if (!_d) {                                                                  \
        asm volatile("{\n\t.reg .pred P1;\n\t"                                  \
            "W_%=:\n\t"                                                         \
            "mbarrier.try_wait.parity.acquire.cta.shared::cta.b64 P1, [%0], %1, 0x989680;\n\t" \
            "@P1 bra.uni D_%=;\n\t"                                             \
            "bra.uni W_%=;\n\t"                                                 \
            "D_%=:\n\t}" :: "r"(_m), "r"(_p) : "memory");                       \
    }                                                                           \
} while (0)

// ---------------------------------------------------------------------------
// batched weight convert fp32 -> fp16 (7 arrays, one launch)
// ---------------------------------------------------------------------------
__global__ __launch_bounds__(256) void conv7(
    const float* __restrict__ s0, f16* __restrict__ d0, int n0,
    const float* __restrict__ s1, f16* __restrict__ d1, int n1,
    const float* __restrict__ s2, f16* __restrict__ d2, int n2,
    const float* __restrict__ s3, f16* __restrict__ d3, int n3,
    const float* __restrict__ s4, f16* __restrict__ d4, int n4,
    const float* __restrict__ s5, f16* __restrict__ d5, int n5,
    const float* __restrict__ s6, f16* __restrict__ d6, int n6)
{
    int j = blockIdx.x * 256 + threadIdx.x;
    const float* s; f16* d;
    if (j < n0) { s = s0; d = d0; }
    else { j -= n0;
    if (j < n1) { s = s1; d = d1; }
    else { j -= n1;
    if (j < n2) { s = s2; d = d2; }
    else { j -= n2;
    if (j < n3) { s = s3; d = d3; }
    else { j -= n3;
    if (j < n4) { s = s4; d = d4; }
    else { j -= n4;
    if (j < n5) { s = s5; d = d5; }
    else { j -= n5;
    if (j >= n6) return;
    s = s6; d = d6; }}}}}}
    float4 v = reinterpret_cast<const float4*>(s)[j];
    reinterpret_cast<uint2*>(d)[j] = make_uint2(
        pack_h2(__float2half(v.x), __float2half(v.y)),
        pack_h2(__float2half(v.z), __float2half(v.w)));
}

// ---------------------------------------------------------------------------
// RMSNorm -> fp16.  IN16: input array is f16 (xres), else f32.
// ---------------------------------------------------------------------------
template<bool IN16>
__global__ __launch_bounds__(256) void rmsnorm_h16(
    const void* __restrict__ xin, const float* __restrict__ w,
    f16* __restrict__ o)
{
    int tkn = blockIdx.x;
    int t = threadIdx.x;
    float f[4];
    if (IN16) {
        const f16* xp = (const f16*)xin;
        uint2 u = reinterpret_cast<const uint2*>(xp + (size_t)tkn * HIDDEN)[t];
        __half2 p0 = *reinterpret_cast<__half2*>(&u.x);
        __half2 p1 = *reinterpret_cast<__half2*>(&u.y);
        f[0] = __low2float(p0); f[1] = __high2float(p0);
        f[2] = __low2float(p1); f[3] = __high2float(p1);
    } else {
        float4 v = reinterpret_cast<const float4*>((const float*)xin + (size_t)tkn * HIDDEN)[t];
        f[0] = v.x; f[1] = v.y; f[2] = v.z; f[3] = v.w;
    }
    float s = f[0]*f[0] + f[1]*f[1] + f[2]*f[2] + f[3]*f[3];
    #pragma unroll
    for (int o2 = 16; o2 > 0; o2 >>= 1) s += __shfl_xor_sync(0xFFFFFFFFu, s, o2);
    __shared__ float ws[8];
    __shared__ float tot_sh;
    if ((t & 31) == 0) ws[t >> 5] = s;
    __syncthreads();
    if (t < 32) {
        float z = (t < 8) ? ws[t] : 0.0f;
        #pragma unroll
        for (int o2 = 4; o2 > 0; o2 >>= 1) z += __shfl_xor_sync(0xFFFFFFFFu, z, o2);
        if (t == 0) tot_sh = z;
    }
    __syncthreads();
    float r = rsqrtf(tot_sh * (1.0f / HIDDEN) + 1e-6f);
    float4 wv = reinterpret_cast<const float4*>(w)[t];
    size_t q = (size_t)tkn * (HIDDEN / 4) + t;
    reinterpret_cast<uint2*>(o)[q] = make_uint2(
        pack_h2(__float2half(f[0] * r * wv.x), __float2half(f[1] * r * wv.y)),
        pack_h2(__float2half(f[2] * r * wv.z), __float2half(f[3] * r * wv.w)));
}

// ---------------------------------------------------------------------------
// Single-B GEMM (CTA 128x128, 4 warps @ 64x64, 3-stage mbarrier ring)
// ---------------------------------------------------------------------------
#define EPI_NONE          0
#define EPI_BIAS_SIGMOID  2
#define EPI_RESADD_F32    3   // aux f32 array
#define EPI_RESADD_F16    4   // aux f16 array

template<int EPI>
__device__ __forceinline__ float epi_apply(float v,
                                           const float* __restrict__ auxf,
                                           const f16* __restrict__ auxh,
                                           size_t idx, int col)
{
    if (EPI == EPI_BIAS_SIGMOID) return fast_sig(v + __ldg(&auxf[col]));
    if (EPI == EPI_RESADD_F32)   return v + __ldg(&auxf[idx]);
    if (EPI == EPI_RESADD_F16)   return v + __half2float(__ldg(&auxh[idx]));
    return v;
}

#define STAGE_B   32768u
#define GEMM_SMEM (3 * 32768 + 64)

template<int EPI, bool OUT16>
__global__ __launch_bounds__(128, 2) void mma_gemm(
    const f16* __restrict__ A, const f16* __restrict__ B,
    float* __restrict__ Cf, f16* __restrict__ Ch,
    const float* __restrict__ auxf, const f16* __restrict__ auxh,
    int M, int K)
{
    extern __shared__ char smem[];
    const uint32_t sb = smem_u32(smem);
    const uint32_t mb = sb + 3u * STAGE_B;
    const int tid = threadIdx.x;
    const int lane = tid & 31;
    const int wid = tid >> 5;
    const int warp_m = wid >> 1;
    const int warp_n = wid & 1;
    const int rowBlock = blockIdx.y * 128;
    const int colBlock = blockIdx.x * 128;
    const int nch = K >> 6;

    const f16* gpA = A + (size_t)rowBlock * K;
    const f16* gpB = B + (size_t)colBlock * K;

    if (tid == 0) {
        #pragma unroll
        for (int s = 0; s < 3; s++) {
            MBAR_INIT(mb + s * 8, 128);
            MBAR_INIT(mb + 24 + s * 8, 4);
        }
    }
    __syncthreads();

    auto issue = [&](int c, int buf) {
        const int kb = c * 64;
        uint32_t st = sb + (uint32_t)buf * STAGE_B;
        #pragma unroll
        for (int i = 0; i < 8; i++) {
            int u = tid + i * 128;
            int r = u >> 3, cc = u & 7;
            cp16(st + r * 128 + ((cc ^ (r & 7)) << 4),
                 gpA + (size_t)r * K + kb + cc * 8);
        }
        #pragma unroll
        for (int i = 0; i < 8; i++) {
            int u = tid + i * 128;
            int r = u >> 3, cc = u & 7;
            cp16(st + 16384u + r * 128 + ((cc ^ (r & 7)) << 4),
                 gpB + (size_t)r * K + kb + cc * 8);
        }
    };

    float acc[4][8][4];
    #pragma unroll
    for (int i = 0; i < 4; i++)
        #pragma unroll
        for (int j = 0; j < 8; j++)
            #pragma unroll
            for (int k = 0; k < 4; k++) acc[i][j][k] = 0.0f;

    int pstage = 0, pphase = 1;
    int cstage = 0, cphase = 0;

    #pragma unroll
    for (int s = 0; s < 3; s++) {
        if (s < nch) {
            MBAR_WAIT(mb + 24 + pstage * 8, pphase);
            issue(s, pstage);
            CP_MBAR_ARRIVE(mb + pstage * 8);
            pstage++; if (pstage == 3) { pstage = 0; pphase ^= 1; }
        }
    }

    const int aRow0 = warp_m * 64 + (lane & 7) + ((lane >> 3) & 1) * 8;
    const int aKh   = (lane >> 4) & 1;
    const int bRow0 = warp_n * 64 + ((lane >> 4) & 1) * 8 + (lane & 7);
    const int bKh   = (lane >> 3) & 1;
    const int swz   = lane & 7;

    for (int c = 0; c < nch; c++) {
        int s = cstage;
        MBAR_WAIT(mb + s * 8, cphase);
        cstage++; if (cstage == 3) { cstage = 0; cphase ^= 1; }

        uint32_t st = sb + (uint32_t)s * STAGE_B;
        #pragma unroll
        for (int ks = 0; ks < 4; ks++) {
            uint32_t afr[4][4];
            #pragma unroll
            for (int mt = 0; mt < 4; mt++) {
                uint32_t roff = (uint32_t)(aRow0 + mt * 16) * 128
                              + (uint32_t)(((ks * 2 + aKh) ^ swz) << 4);
                ldsm4(afr[mt], st + roff);
            }
            uint32_t bfr[8][2];
            #pragma unroll
            for (int p = 0; p < 4; p++) {
                uint32_t roff = (uint32_t)(bRow0 + p * 16) * 128
                              + (uint32_t)(((ks * 2 + bKh) ^ swz) << 4);
                uint32_t t4[4];
                ldsm4(t4, st + 16384u + roff);
                bfr[2 * p][0] = t4[0]; bfr[2 * p][1] = t4[1];
                bfr[2 * p + 1][0] = t4[2]; bfr[2 * p + 1][1] = t4[3];
            }
            #pragma unroll
            for (int mt = 0; mt < 4; mt++)
                #pragma unroll
                for (int nt = 0; nt < 8; nt++)
                    mma_f16(acc[mt][nt], afr[mt], bfr[nt][0], bfr[nt][1]);
        }

        if (lane == 0) MBAR_ARRIVE(mb + 24 + s * 8);

        if (c + 3 < nch) {
            MBAR_WAIT(mb + 24 + pstage * 8, pphase);
            issue(c + 3, pstage);
            CP_MBAR_ARRIVE(mb + pstage * 8);
            pstage++; if (pstage == 3) { pstage = 0; pphase ^= 1; }
        }
    }

    #pragma unroll
    for (int mt = 0; mt < 4; mt++) {
        #pragma unroll
        for (int nt = 0; nt < 8; nt++) {
            int col = colBlock + warp_n * 64 + nt * 8 + (lane & 3) * 2;
            #pragma unroll
            for (int half = 0; half < 2; half++) {
                int row = rowBlock + warp_m * 64 + mt * 16 + (lane >> 2) + half * 8;
                size_t idx = (size_t)row * M + col;
                float f0 = epi_apply<EPI>(acc[mt][nt][half * 2 + 0], auxf, auxh, idx, col);
                float f1 = epi_apply<EPI>(acc[mt][nt][half * 2 + 1], auxf, auxh, idx + 1, col + 1);
                if (OUT16) {
                    *reinterpret_cast<uint32_t*>(Ch + idx) =
                        pack_h2(__float2half(f0), __float2half(f1));
                } else {
                    *reinterpret_cast<float2*>(Cf + idx) = make_float2(f0, f1);
                }
            }
        }
    }
}

// ---------------------------------------------------------------------------
// Dual-B GEMM: T1 = A@B1^T, T2 = A@B2^T on one A pass.
// FUSE_SILU=1: C1 = silu(T1)*T2        (MLP gate+up)
// FUSE_SILU=0: C1 = T1, C2 = sigmoid(T2) (w_in + w_gate)
// ---------------------------------------------------------------------------
template<int FUSE_SILU>
__global__ __launch_bounds__(128, 2) void mma_gemm_dual(
    const f16* __restrict__ A, const f16* __restrict__ B1,
    const f16* __restrict__ B2, f16* __restrict__ C1, f16* __restrict__ C2,
    int M, int K)
{
    extern __shared__ char smem[];
    const uint32_t sb = smem_u32(smem);
    const uint32_t mb = sb + 3u * STAGE_B;
    const int tid = threadIdx.x;
    const int lane = tid & 31;
    const int wid = tid >> 5;
    const int warp_m = wid >> 1;
    const int warp_n = wid & 1;
    const int rowBlock = blockIdx.y * 128;
    const int colBlock = blockIdx.x * 64;
    const int nch = K >> 6;

    const f16* gpA  = A  + (size_t)rowBlock * K;
    const f16* gpB1 = B1 + (size_t)colBlock * K;
    const f16* gpB2 = B2 + (size_t)colBlock * K;

    if (tid == 0) {
        #pragma unroll
        for (int s = 0; s < 3; s++) {
            MBAR_INIT(mb + s * 8, 128);
            MBAR_INIT(mb + 24 + s * 8, 4);
        }
    }
    __syncthreads();

    auto issue = [&](int c, int buf) {
        const int kb = c * 64;
        uint32_t st = sb + (uint32_t)buf * STAGE_B;
        #pragma unroll
        for (int i = 0; i < 8; i++) {
            int u = tid + i * 128;
            int r = u >> 3, cc = u & 7;
            cp16(st + r * 128 + ((cc ^ (r & 7)) << 4),
                 gpA + (size_t)r * K + kb + cc * 8);
        }
        #pragma unroll
        for (int i = 0; i < 4; i++) {
            int u = tid + i * 128;
            int r = u >> 3, cc = u & 7;
            cp16(st + 16384u + r * 128 + ((cc ^ (r & 7)) << 4),
                 gpB1 + (size_t)r * K + kb + cc * 8);
        }
        #pragma unroll
        for (int i = 0; i < 4; i++) {
            int u = tid + i * 128;
            int r = u >> 3, cc = u & 7;
            cp16(st + 24576u + r * 128 + ((cc ^ (r & 7)) << 4),
                 gpB2 + (size_t)r * K + kb + cc * 8);
        }
    };

    float acc1[4][4][4], acc2[4][4][4];
    #pragma unroll
    for (int i = 0; i < 4; i++)
        #pragma unroll
        for (int j = 0; j < 4; j++)
            #pragma unroll
            for (int k = 0; k < 4; k++) { acc1[i][j][k] = 0.0f; acc2[i][j][k] = 0.0f; }

    int pstage = 0, pphase = 1;
    int cstage = 0, cphase = 0;

    #pragma unroll
    for (int s = 0; s < 3; s++) {
        if (s < nch) {
            MBAR_WAIT(mb + 24 + pstage * 8, pphase);
            issue(s, pstage);
            CP_MBAR_ARRIVE(mb + pstage * 8);
            pstage++; if (pstage == 3) { pstage = 0; pphase ^= 1; }
        }
    }

    const int aRow0 = warp_m * 64 + (lane & 7) + ((lane >> 3) & 1) * 8;
    const int aKh   = (lane >> 4) & 1;
    const int bRow0 = warp_n * 32 + ((lane >> 4) & 1) * 8 + (lane & 7);
    const int bKh   = (lane >> 3) & 1;
    const int swz   = lane & 7;

    for (int c = 0; c < nch; c++) {
        int s = cstage;
        MBAR_WAIT(mb + s * 8, cphase);
        cstage++; if (cstage == 3) { cstage = 0; cphase ^= 1; }

        uint32_t st = sb + (uint32_t)s * STAGE_B;
        #pragma unroll
        for (int ks = 0; ks < 4; ks++) {
            uint32_t afr[4][4];
            #pragma unroll
            for (int mt = 0; mt < 4; mt++) {
                uint32_t roff = (uint32_t)(aRow0 + mt * 16) * 128
                              + (uint32_t)(((ks * 2 + aKh) ^ swz) << 4);
                ldsm4(afr[mt], st + roff);
            }
            uint32_t b1fr[4][2], b2fr[4][2];
            #pragma unroll
            for (int p = 0; p < 2; p++) {
                uint32_t roff = (uint32_t)(bRow0 + p * 16) * 128
                              + (uint32_t)(((ks * 2 + bKh) ^ swz) << 4);
                uint32_t t4[4];
                ldsm4(t4, st + 16384u + roff);
                b1fr[2 * p][0] = t4[0]; b1fr[2 * p][1] = t4[1];
                b1fr[2 * p + 1][0] = t4[2]; b1fr[2 * p + 1][1] = t4[3];
                ldsm4(t4, st + 24576u + roff);
                b2fr[2 * p][0] = t4[0]; b2fr[2 * p][1] = t4[1];
                b2fr[2 * p + 1][0] = t4[2]; b2fr[2 * p + 1][1] = t4[3];
            }
            #pragma unroll
            for (int mt = 0; mt < 4; mt++)
                #pragma unroll
                for (int nt = 0; nt < 4; nt++)
                    mma_f16(acc1[mt][nt], afr[mt], b1fr[nt][0], b1fr[nt][1]);
            #pragma unroll
            for (int mt = 0; mt < 4; mt++)
                #pragma unroll
                for (int nt = 0; nt < 4; nt++)
                    mma_f16(acc2[mt][nt], afr[mt], b2fr[nt][0], b2fr[nt][1]);
        }

        if (lane == 0) MBAR_ARRIVE(mb + 24 + s * 8);

        if (c + 3 < nch) {
            MBAR_WAIT(mb + 24 + pstage * 8, pphase);
            issue(c + 3, pstage);
            CP_MBAR_ARRIVE(mb + pstage * 8);
            pstage++; if (pstage == 3) { pstage = 0; pphase ^= 1; }
        }
    }

    #pragma unroll
    for (int mt = 0; mt < 4; mt++) {
        #pragma unroll
        for (int nt = 0; nt < 4; nt++) {
            int col = colBlock + warp_n * 32 + nt * 8 + (lane & 3) * 2;
            #pragma unroll
            for (int half = 0; half < 2; half++) {
                int row = rowBlock + warp_m * 64 + mt * 16 + (lane >> 2) + half * 8;
                size_t idx = (size_t)row * M + col;
                float t10 = acc1[mt][nt][half * 2 + 0], t20 = acc2[mt][nt][half * 2 + 0];
                float t11 = acc1[mt][nt][half * 2 + 1], t21 = acc2[mt][nt][half * 2 + 1];
                if (FUSE_SILU) {
                    float f0 = t10 * fast_sig(t10) * t20;
                    float f1 = t11 * fast_sig(t11) * t21;
                    *reinterpret_cast<uint32_t*>(C1 + idx) =
                        pack_h2(__float2half(f0), __float2half(f1));
                } else {
                    *reinterpret_cast<uint32_t*>(C1 + idx) =
                        pack_h2(__float2half(t10), __float2half(t11));
                    *reinterpret_cast<uint32_t*>(C2 + idx) =
                        pack_h2(__float2half(fast_sig(t20)), __float2half(fast_sig(t21)));
                }
            }
        }
    }
}

// ---------------------------------------------------------------------------
// Parallel Hawk scan, recompute style ('a' is f16)
// ---------------------------------------------------------------------------
__global__ __launch_bounds__(256) void scan_part1(
    const f16* __restrict__ xin, const f16* __restrict__ a,
    float* __restrict__ csum)
{
    int id = blockIdx.x * 256 + threadIdx.x;
    int chunk = id >> 13;
    int chp = id & (NCHAN - 1);
    int b = chp >> 11;
    int d = chp & (DREC - 1);
    size_t base = ((size_t)b * TLEN + (size_t)chunk * SCHUNK) * DREC + d;

    float h = 0.0f, Aacc = 1.0f;
    #pragma unroll 4
    for (int t = 0; t < SCHUNK; t++) {
        size_t idx = base + (size_t)t * DREC;
        float at = __half2float(__ldg(&a[idx]));
        float xt = __half2float(__ldg(&xin[idx]));
        float s = sqrtf(fmaf(-at, at, 1.0f) + 1e-8f);
        h = fmaf(at, h, s * xt);
        Aacc *= at;
    }
    csum[(size_t)chunk * NCHAN + chp] = Aacc;
    csum[(size_t)NCHUNKS * NCHAN + (size_t)chunk * NCHAN + chp] = h;
}

__global__ __launch_bounds__(256) void scan_part2(
    const float* __restrict__ csum, float* __restrict__ carry)
{
    int chp = blockIdx.x * 256 + threadIdx.x;
    float h = 0.0f;
    #pragma unroll
    for (int c = 0; c < NCHUNKS; c++) {
        carry[(size_t)c * NCHAN + chp] = h;
        float Ac = __ldg(&csum[(size_t)c * NCHAN + chp]);
        float hc = __ldg(&csum[(size_t)NCHUNKS * NCHAN + (size_t)c * NCHAN + chp]);
        h = fmaf(Ac, h, hc);
    }
}

__global__ __launch_bounds__(256) void scan_part3(
    const f16* __restrict__ xin, const f16* __restrict__ a,
    const f16* __restrict__ gate, const float* __restrict__ carry,
    f16* __restrict__ y)
{
    int id = blockIdx.x * 256 + threadIdx.x;
    int chunk = id >> 13;
    int chp = id & (NCHAN - 1);
    int b = chp >> 11;
    int d = chp & (DREC - 1);
    size_t base = ((size_t)b * TLEN + (size_t)chunk * SCHUNK) * DREC + d;

    float h = __ldg(&carry[(size_t)chunk * NCHAN + chp]);
    #pragma unroll 4
    for (int t = 0; t < SCHUNK; t++) {
        size_t idx = base + (size_t)t * DREC;
        float at = __half2float(__ldg(&a[idx]));
        float xt = __half2float(__ldg(&xin[idx]));
        float gt = __half2float(__ldg(&gate[idx]));
        float s = sqrtf(fmaf(-at, at, 1.0f) + 1e-8f);
        h = fmaf(at, h, s * xt);
        y[idx] = __float2half(gt * h);
    }
}

// ---------------------------------------------------------------------------
// Launch
// ---------------------------------------------------------------------------
#define SYM(p, s) cudaGetSymbolAddress((void**)&p, s)

extern "C" void kernel_launch(void* const* d_in, const int* in_sizes, int n_in,
                              void* d_out, int out_size)
{
    const float* x       = (const float*)d_in[0];
    const float* ln1_w   = (const float*)d_in[1];
    const float* ln2_w   = (const float*)d_in[2];
    const float* w_in    = (const float*)d_in[3];
    const float* w_gate  = (const float*)d_in[4];
    const float* a_param = (const float*)d_in[5];
    const float* w_a     = (const float*)d_in[6];
    const float* w_out   = (const float*)d_in[7];
    const float* w_mg    = (const float*)d_in[8];
    const float* w_mu    = (const float*)d_in[9];
    const float* w_md    = (const float*)d_in[10];
    float* out = (float*)d_out;

    f16 *hh, *h2h, *xinh, *gateh, *ah, *yh, *muh, *xresh;
    float *csum, *carry;
    f16 *wi, *wg, *wa, *wo, *wmgp, *wmup, *wmdp;

    SYM(hh, g_h);     SYM(h2h, g_h2);
    SYM(xinh, g_xin); SYM(gateh, g_gate); SYM(ah, g_a);
    SYM(yh, g_y);     SYM(muh, g_mu);     SYM(xresh, g_xres);
    SYM(csum, g_csum); SYM(carry, g_carry);
    SYM(wi, g_wi);  SYM(wg, g_wg);  SYM(wa, g_wa);  SYM(wo, g_wo);
    SYM(wmgp, g_wmg); SYM(wmup, g_wmu); SYM(wmdp, g_wmd);

    cudaFuncSetAttribute(mma_gemm<EPI_BIAS_SIGMOID, true>,  cudaFuncAttributeMaxDynamicSharedMemorySize, GEMM_SMEM);
    cudaFuncSetAttribute(mma_gemm<EPI_RESADD_F32, true>,    cudaFuncAttributeMaxDynamicSharedMemorySize, GEMM_SMEM);
    cudaFuncSetAttribute(mma_gemm<EPI_RESADD_F16, false>,   cudaFuncAttributeMaxDynamicSharedMemorySize, GEMM_SMEM);
    cudaFuncSetAttribute(mma_gemm_dual<0>,                  cudaFuncAttributeMaxDynamicSharedMemorySize, GEMM_SMEM);
    cudaFuncSetAttribute(mma_gemm_dual<1>,                  cudaFuncAttributeMaxDynamicSharedMemorySize, GEMM_SMEM);

    dim3 blk(256);
    dim3 gblk(128);
    const int GY = NTOK / 128;   // 128

    const int n_ih = DREC * HIDDEN / 4;   // 524288
    const int n_aa = DREC * DREC / 4;     // 1048576
    const int n_mh = INTER * HIDDEN / 4;  // 1048576

    // convert all 7 weights to fp16
    {
        int total = 3 * n_ih + n_aa + 3 * n_mh;
        conv7<<<(total + 255) / 256, blk>>>(
            w_in, wi, n_ih,
            w_gate, wg, n_ih,
            w_a, wa, n_aa,
            w_out, wo, n_ih,
            w_mg, wmgp, n_mh,
            w_mu, wmup, n_mh,
            w_md, wmdp, n_mh);
    }

    // h = rmsnorm(x, ln1)
    rmsnorm_h16<false><<<NTOK, blk>>>(x, ln1_w, hh);

    // fused: xin = h@Wi^T, gate = sigmoid(h@Wg^T)
    mma_gemm_dual<0><<<dim3(DREC / 64, GY), gblk, GEMM_SMEM>>>(
        hh, wi, wg, xinh, gateh, DREC, HIDDEN);

    // a = sigmoid(a_param + xin @ w_a^T)  (f16)
    mma_gemm<EPI_BIAS_SIGMOID, true><<<dim3(DREC / 128, GY), gblk, GEMM_SMEM>>>(
        xinh, wa, nullptr, ah, a_param, nullptr, DREC, DREC);

    // scan
    scan_part1<<<(NCHUNKS * NCHAN) / 256, blk>>>(xinh, ah, csum);
    scan_part2<<<NCHAN / 256, blk>>>(csum, carry);
    scan_part3<<<(NCHUNKS * NCHAN) / 256, blk>>>(xinh, ah, gateh, carry, yh);

    // xres = x + y @ w_out^T  (f16 out, f32 aux)
    mma_gemm<EPI_RESADD_F32, true><<<dim3(HIDDEN / 128, GY), gblk, GEMM_SMEM>>>(
        yh, wo, nullptr, xresh, x, nullptr, HIDDEN, DREC);

    // h2 = rmsnorm(xres, ln2)  (f16 in)
    rmsnorm_h16<true><<<NTOK, blk>>>(xresh, ln2_w, h2h);

    // fused MLP gate+up: mu = silu(h2@Wg^T) * (h2@Wu^T)
    mma_gemm_dual<1><<<dim3(INTER / 64, GY), gblk, GEMM_SMEM>>>(
        h2h, wmgp, wmup, muh, nullptr, INTER, HIDDEN);

    // out = xres + mu @ w_mlp_down^T  (f32 out, f16 aux)
    mma_gemm<EPI_RESADD_F16, false><<<dim3(HIDDEN / 128, GY), gblk, GEMM_SMEM>>>(
        muh, wmdp, out, nullptr, nullptr, xresh, HIDDEN, INTER);
}

// round 14
// speedup vs baseline: 1.5019x; 1.5019x over previous
#include <cuda_runtime.h>
#include <cuda_fp16.h>
#include <math.h>
#include <stdint.h>

// ---------------------------------------------------------------------------
// HawkBlock: fp16 mma.sync GEMMs, f32 accum, 3-stage mbarrier ring.
// Dual-B fusions: (w_in + w_gate) and (mlp gate + up -> silu fused).
// Fast-math epilogues, f16 'a' + f16 xres, recompute-style parallel scan.
// (Re-bench of R13 — R13's wall time showed ~1.55x uniform inflation with
//  identical per-cycle metrics => DVFS/throttle noise, not code.)
// ---------------------------------------------------------------------------

#define NTOK   16384
#define HIDDEN 1024
#define DREC   2048
#define INTER  4096
#define TLEN   4096
#define NB     4

#define SCHUNK   64
#define NCHUNKS  (TLEN / SCHUNK)   // 64
#define NCHAN    (NB * DREC)       // 8192

typedef __half f16;

// ---- static scratch ----
__device__ f16   g_h   [(size_t)NTOK * HIDDEN];
__device__ f16   g_h2  [(size_t)NTOK * HIDDEN];
__device__ f16   g_xres[(size_t)NTOK * HIDDEN];
__device__ f16   g_xin [(size_t)NTOK * DREC];
__device__ f16   g_gate[(size_t)NTOK * DREC];
__device__ f16   g_a   [(size_t)NTOK * DREC];
__device__ f16   g_y   [(size_t)NTOK * DREC];
__device__ f16   g_mu  [(size_t)NTOK * INTER];
__device__ float g_csum [2 * NCHUNKS * NCHAN];
__device__ float g_carry[NCHUNKS * NCHAN];

// ---- fp16 weights ----
__device__ f16 g_wi [(size_t)DREC * HIDDEN];
__device__ f16 g_wg [(size_t)DREC * HIDDEN];
__device__ f16 g_wa [(size_t)DREC * DREC];
__device__ f16 g_wo [(size_t)HIDDEN * DREC];
__device__ f16 g_wmg[(size_t)INTER * HIDDEN];
__device__ f16 g_wmu[(size_t)INTER * HIDDEN];
__device__ f16 g_wmd[(size_t)HIDDEN * INTER];

// ---------------------------------------------------------------------------
// helpers
// ---------------------------------------------------------------------------
__device__ __forceinline__ uint32_t smem_u32(const void* p) {
    uint32_t a;
    asm("{ .reg .u64 t; cvta.to.shared.u64 t, %1; cvt.u32.u64 %0, t; }"
        : "=r"(a) : "l"(p));
    return a;
}
__device__ __forceinline__ void cp16(uint32_t dst, const void* src) {
    asm volatile("cp.async.cg.shared.global [%0], [%1], 16;"
                 :: "r"(dst), "l"(src));
}
__device__ __forceinline__ void ldsm4(uint32_t (&r)[4], uint32_t addr) {
    asm volatile("ldmatrix.sync.aligned.m8n8.x4.shared.b16 {%0,%1,%2,%3}, [%4];"
                 : "=r"(r[0]), "=r"(r[1]), "=r"(r[2]), "=r"(r[3]) : "r"(addr));
}
__device__ __forceinline__ void mma_f16(float (&d)[4], const uint32_t (&a)[4],
                                        uint32_t b0, uint32_t b1) {
    asm volatile("mma.sync.aligned.m16n8k16.row.col.f32.f16.f16.f32 "
                 "{%0,%1,%2,%3}, {%4,%5,%6,%7}, {%8,%9}, {%0,%1,%2,%3};"
                 : "+f"(d[0]), "+f"(d[1]), "+f"(d[2]), "+f"(d[3])
                 : "r"(a[0]), "r"(a[1]), "r"(a[2]), "r"(a[3]), "r"(b0), "r"(b1));
}
__device__ __forceinline__ uint32_t pack_h2(f16 a, f16 b) {
    __half2 t = __halves2half2(a, b);
    return *reinterpret_cast<uint32_t*>(&t);
}
__device__ __forceinline__ float fast_sig(float v) {
    return __fdividef(1.0f, 1.0f + __expf(-v));
}

// ---- mbarrier primitives ----
#define MBAR_INIT(addr, cnt) \
    asm volatile("mbarrier.init.shared.b64 [%0], %1;" \
                 :: "r"((uint32_t)(addr)), "r"((uint32_t)(cnt)) : "memory")
#define MBAR_ARRIVE(addr) \
    asm volatile("mbarrier.arrive.shared.b64 _, [%0];" \
                 :: "r"((uint32_t)(addr)) : "memory")
#define CP_MBAR_ARRIVE(addr) \
    asm volatile("cp.async.mbarrier.arrive.noinc.shared.b64 [%0];" \
                 :: "r"((uint32_t)(addr)) : "memory")
#define MBAR_WAIT(addr, parity) do {                                            \
    uint32_t _m = (uint32_t)(addr); uint32_t _p = (uint32_t)(parity);           \
    uint32_t _d;                                                                \
    asm volatile("{\n\t.reg .pred p;\n\t"                                       \
        "mbarrier.try_wait.parity.acquire.cta.shared::cta.b64 p, [%1], %2;\n\t" \
        "selp.b32 %0, 1, 0, p;\n\t}" : "=r"(_d) : "r"(_m), "r"(_p) : "memory"); \
    if (!_d) {                                                                  \
        asm volatile("{\n\t.reg .pred P1;\n\t"                                  \
            "W_%=:\n\t"                                                         \
            "mbarrier.try_wait.parity.acquire.cta.shared::cta.b64 P1, [%0], %1, 0x989680;\n\t" \
            "@P1 bra.uni D_%=;\n\t"                                             \
            "bra.uni W_%=;\n\t"                                                 \
            "D_%=:\n\t}" :: "r"(_m), "r"(_p) : "memory");                       \
    }                                                                           \
} while (0)

// ---------------------------------------------------------------------------
// batched weight convert fp32 -> fp16 (7 arrays, one launch)
// ---------------------------------------------------------------------------
__global__ __launch_bounds__(256) void conv7(
    const float* __restrict__ s0, f16* __restrict__ d0, int n0,
    const float* __restrict__ s1, f16* __restrict__ d1, int n1,
    const float* __restrict__ s2, f16* __restrict__ d2, int n2,
    const float* __restrict__ s3, f16* __restrict__ d3, int n3,
    const float* __restrict__ s4, f16* __restrict__ d4, int n4,
    const float* __restrict__ s5, f16* __restrict__ d5, int n5,
    const float* __restrict__ s6, f16* __restrict__ d6, int n6)
{
    int j = blockIdx.x * 256 + threadIdx.x;
    const float* s; f16* d;
    if (j < n0) { s = s0; d = d0; }
    else { j -= n0;
    if (j < n1) { s = s1; d = d1; }
    else { j -= n1;
    if (j < n2) { s = s2; d = d2; }
    else { j -= n2;
    if (j < n3) { s = s3; d = d3; }
    else { j -= n3;
    if (j < n4) { s = s4; d = d4; }
    else { j -= n4;
    if (j < n5) { s = s5; d = d5; }
    else { j -= n5;
    if (j >= n6) return;
    s = s6; d = d6; }}}}}}
    float4 v = reinterpret_cast<const float4*>(s)[j];
    reinterpret_cast<uint2*>(d)[j] = make_uint2(
        pack_h2(__float2half(v.x), __float2half(v.y)),
        pack_h2(__float2half(v.z), __float2half(v.w)));
}

// ---------------------------------------------------------------------------
// RMSNorm -> fp16.  IN16: input array is f16 (xres), else f32.
// ---------------------------------------------------------------------------
template<bool IN16>
__global__ __launch_bounds__(256) void rmsnorm_h16(
    const void* __restrict__ xin, const float* __restrict__ w,
    f16* __restrict__ o)
{
    int tkn = blockIdx.x;
    int t = threadIdx.x;
    float f[4];
    if (IN16) {
        const f16* xp = (const f16*)xin;
        uint2 u = reinterpret_cast<const uint2*>(xp + (size_t)tkn * HIDDEN)[t];
        __half2 p0 = *reinterpret_cast<__half2*>(&u.x);
        __half2 p1 = *reinterpret_cast<__half2*>(&u.y);
        f[0] = __low2float(p0); f[1] = __high2float(p0);
        f[2] = __low2float(p1); f[3] = __high2float(p1);
    } else {
        float4 v = reinterpret_cast<const float4*>((const float*)xin + (size_t)tkn * HIDDEN)[t];
        f[0] = v.x; f[1] = v.y; f[2] = v.z; f[3] = v.w;
    }
    float s = f[0]*f[0] + f[1]*f[1] + f[2]*f[2] + f[3]*f[3];
    #pragma unroll
    for (int o2 = 16; o2 > 0; o2 >>= 1) s += __shfl_xor_sync(0xFFFFFFFFu, s, o2);
    __shared__ float ws[8];
    __shared__ float tot_sh;
    if ((t & 31) == 0) ws[t >> 5] = s;
    __syncthreads();
    if (t < 32) {
        float z = (t < 8) ? ws[t] : 0.0f;
        #pragma unroll
        for (int o2 = 4; o2 > 0; o2 >>= 1) z += __shfl_xor_sync(0xFFFFFFFFu, z, o2);
        if (t == 0) tot_sh = z;
    }
    __syncthreads();
    float r = rsqrtf(tot_sh * (1.0f / HIDDEN) + 1e-6f);
    float4 wv = reinterpret_cast<const float4*>(w)[t];
    size_t q = (size_t)tkn * (HIDDEN / 4) + t;
    reinterpret_cast<uint2*>(o)[q] = make_uint2(
        pack_h2(__float2half(f[0] * r * wv.x), __float2half(f[1] * r * wv.y)),
        pack_h2(__float2half(f[2] * r * wv.z), __float2half(f[3] * r * wv.w)));
}

// ---------------------------------------------------------------------------
// Single-B GEMM (CTA 128x128, 4 warps @ 64x64, 3-stage mbarrier ring)
// ---------------------------------------------------------------------------
#define EPI_NONE          0
#define EPI_BIAS_SIGMOID  2
#define EPI_RESADD_F32    3   // aux f32 array
#define EPI_RESADD_F16    4   // aux f16 array

template<int EPI>
__device__ __forceinline__ float epi_apply(float v,
                                           const float* __restrict__ auxf,
                                           const f16* __restrict__ auxh,
                                           size_t idx, int col)
{
    if (EPI == EPI_BIAS_SIGMOID) return fast_sig(v + __ldg(&auxf[col]));
    if (EPI == EPI_RESADD_F32)   return v + __ldg(&auxf[idx]);
    if (EPI == EPI_RESADD_F16)   return v + __half2float(__ldg(&auxh[idx]));
    return v;
}

#define STAGE_B   32768u
#define GEMM_SMEM (3 * 32768 + 64)

template<int EPI, bool OUT16>
__global__ __launch_bounds__(128, 2) void mma_gemm(
    const f16* __restrict__ A, const f16* __restrict__ B,
    float* __restrict__ Cf, f16* __restrict__ Ch,
    const float* __restrict__ auxf, const f16* __restrict__ auxh,
    int M, int K)
{
    extern __shared__ char smem[];
    const uint32_t sb = smem_u32(smem);
    const uint32_t mb = sb + 3u * STAGE_B;
    const int tid = threadIdx.x;
    const int lane = tid & 31;
    const int wid = tid >> 5;
    const int warp_m = wid >> 1;
    const int warp_n = wid & 1;
    const int rowBlock = blockIdx.y * 128;
    const int colBlock = blockIdx.x * 128;
    const int nch = K >> 6;

    const f16* gpA = A + (size_t)rowBlock * K;
    const f16* gpB = B + (size_t)colBlock * K;

    if (tid == 0) {
        #pragma unroll
        for (int s = 0; s < 3; s++) {
            MBAR_INIT(mb + s * 8, 128);
            MBAR_INIT(mb + 24 + s * 8, 4);
        }
    }
    __syncthreads();

    auto issue = [&](int c, int buf) {
        const int kb = c * 64;
        uint32_t st = sb + (uint32_t)buf * STAGE_B;
        #pragma unroll
        for (int i = 0; i < 8; i++) {
            int u = tid + i * 128;
            int r = u >> 3, cc = u & 7;
            cp16(st + r * 128 + ((cc ^ (r & 7)) << 4),
                 gpA + (size_t)r * K + kb + cc * 8);
        }
        #pragma unroll
        for (int i = 0; i < 8; i++) {
            int u = tid + i * 128;
            int r = u >> 3, cc = u & 7;
            cp16(st + 16384u + r * 128 + ((cc ^ (r & 7)) << 4),
                 gpB + (size_t)r * K + kb + cc * 8);
        }
    };

    float acc[4][8][4];
    #pragma unroll
    for (int i = 0; i < 4; i++)
        #pragma unroll
        for (int j = 0; j < 8; j++)
            #pragma unroll
            for (int k = 0; k < 4; k++) acc[i][j][k] = 0.0f;

    int pstage = 0, pphase = 1;
    int cstage = 0, cphase = 0;

    #pragma unroll
    for (int s = 0; s < 3; s++) {
        if (s < nch) {
            MBAR_WAIT(mb + 24 + pstage * 8, pphase);
            issue(s, pstage);
            CP_MBAR_ARRIVE(mb + pstage * 8);
            pstage++; if (pstage == 3) { pstage = 0; pphase ^= 1; }
        }
    }

    const int aRow0 = warp_m * 64 + (lane & 7) + ((lane >> 3) & 1) * 8;
    const int aKh   = (lane >> 4) & 1;
    const int bRow0 = warp_n * 64 + ((lane >> 4) & 1) * 8 + (lane & 7);
    const int bKh   = (lane >> 3) & 1;
    const int swz   = lane & 7;

    for (int c = 0; c < nch; c++) {
        int s = cstage;
        MBAR_WAIT(mb + s * 8, cphase);
        cstage++; if (cstage == 3) { cstage = 0; cphase ^= 1; }

        uint32_t st = sb + (uint32_t)s * STAGE_B;
        #pragma unroll
        for (int ks = 0; ks < 4; ks++) {
            uint32_t afr[4][4];
            #pragma unroll
            for (int mt = 0; mt < 4; mt++) {
                uint32_t roff = (uint32_t)(aRow0 + mt * 16) * 128
                              + (uint32_t)(((ks * 2 + aKh) ^ swz) << 4);
                ldsm4(afr[mt], st + roff);
            }
            uint32_t bfr[8][2];
            #pragma unroll
            for (int p = 0; p < 4; p++) {
                uint32_t roff = (uint32_t)(bRow0 + p * 16) * 128
                              + (uint32_t)(((ks * 2 + bKh) ^ swz) << 4);
                uint32_t t4[4];
                ldsm4(t4, st + 16384u + roff);
                bfr[2 * p][0] = t4[0]; bfr[2 * p][1] = t4[1];
                bfr[2 * p + 1][0] = t4[2]; bfr[2 * p + 1][1] = t4[3];
            }
            #pragma unroll
            for (int mt = 0; mt < 4; mt++)
                #pragma unroll
                for (int nt = 0; nt < 8; nt++)
                    mma_f16(acc[mt][nt], afr[mt], bfr[nt][0], bfr[nt][1]);
        }

        if (lane == 0) MBAR_ARRIVE(mb + 24 + s * 8);

        if (c + 3 < nch) {
            MBAR_WAIT(mb + 24 + pstage * 8, pphase);
            issue(c + 3, pstage);
            CP_MBAR_ARRIVE(mb + pstage * 8);
            pstage++; if (pstage == 3) { pstage = 0; pphase ^= 1; }
        }
    }

    #pragma unroll
    for (int mt = 0; mt < 4; mt++) {
        #pragma unroll
        for (int nt = 0; nt < 8; nt++) {
            int col = colBlock + warp_n * 64 + nt * 8 + (lane & 3) * 2;
            #pragma unroll
            for (int half = 0; half < 2; half++) {
                int row = rowBlock + warp_m * 64 + mt * 16 + (lane >> 2) + half * 8;
                size_t idx = (size_t)row * M + col;
                float f0 = epi_apply<EPI>(acc[mt][nt][half * 2 + 0], auxf, auxh, idx, col);
                float f1 = epi_apply<EPI>(acc[mt][nt][half * 2 + 1], auxf, auxh, idx + 1, col + 1);
                if (OUT16) {
                    *reinterpret_cast<uint32_t*>(Ch + idx) =
                        pack_h2(__float2half(f0), __float2half(f1));
                } else {
                    *reinterpret_cast<float2*>(Cf + idx) = make_float2(f0, f1);
                }
            }
        }
    }
}

// ---------------------------------------------------------------------------
// Dual-B GEMM: T1 = A@B1^T, T2 = A@B2^T on one A pass.
// FUSE_SILU=1: C1 = silu(T1)*T2        (MLP gate+up)
// FUSE_SILU=0: C1 = T1, C2 = sigmoid(T2) (w_in + w_gate)
// ---------------------------------------------------------------------------
template<int FUSE_SILU>
__global__ __launch_bounds__(128, 2) void mma_gemm_dual(
    const f16* __restrict__ A, const f16* __restrict__ B1,
    const f16* __restrict__ B2, f16* __restrict__ C1, f16* __restrict__ C2,
    int M, int K)
{
    extern __shared__ char smem[];
    const uint32_t sb = smem_u32(smem);
    const uint32_t mb = sb + 3u * STAGE_B;
    const int tid = threadIdx.x;
    const int lane = tid & 31;
    const int wid = tid >> 5;
    const int warp_m = wid >> 1;
    const int warp_n = wid & 1;
    const int rowBlock = blockIdx.y * 128;
    const int colBlock = blockIdx.x * 64;
    const int nch = K >> 6;

    const f16* gpA  = A  + (size_t)rowBlock * K;
    const f16* gpB1 = B1 + (size_t)colBlock * K;
    const f16* gpB2 = B2 + (size_t)colBlock * K;

    if (tid == 0) {
        #pragma unroll
        for (int s = 0; s < 3; s++) {
            MBAR_INIT(mb + s * 8, 128);
            MBAR_INIT(mb + 24 + s * 8, 4);
        }
    }
    __syncthreads();

    auto issue = [&](int c, int buf) {
        const int kb = c * 64;
        uint32_t st = sb + (uint32_t)buf * STAGE_B;
        #pragma unroll
        for (int i = 0; i < 8; i++) {
            int u = tid + i * 128;
            int r = u >> 3, cc = u & 7;
            cp16(st + r * 128 + ((cc ^ (r & 7)) << 4),
                 gpA + (size_t)r * K + kb + cc * 8);
        }
        #pragma unroll
        for (int i = 0; i < 4; i++) {
            int u = tid + i * 128;
            int r = u >> 3, cc = u & 7;
            cp16(st + 16384u + r * 128 + ((cc ^ (r & 7)) << 4),
                 gpB1 + (size_t)r * K + kb + cc * 8);
        }
        #pragma unroll
        for (int i = 0; i < 4; i++) {
            int u = tid + i * 128;
            int r = u >> 3, cc = u & 7;
            cp16(st + 24576u + r * 128 + ((cc ^ (r & 7)) << 4),
                 gpB2 + (size_t)r * K + kb + cc * 8);
        }
    };

    float acc1[4][4][4], acc2[4][4][4];
    #pragma unroll
    for (int i = 0; i < 4; i++)
        #pragma unroll
        for (int j = 0; j < 4; j++)
            #pragma unroll
            for (int k = 0; k < 4; k++) { acc1[i][j][k] = 0.0f; acc2[i][j][k] = 0.0f; }

    int pstage = 0, pphase = 1;
    int cstage = 0, cphase = 0;

    #pragma unroll
    for (int s = 0; s < 3; s++) {
        if (s < nch) {
            MBAR_WAIT(mb + 24 + pstage * 8, pphase);
            issue(s, pstage);
            CP_MBAR_ARRIVE(mb + pstage * 8);
            pstage++; if (pstage == 3) { pstage = 0; pphase ^= 1; }
        }
    }

    const int aRow0 = warp_m * 64 + (lane & 7) + ((lane >> 3) & 1) * 8;
    const int aKh   = (lane >> 4) & 1;
    const int bRow0 = warp_n * 32 + ((lane >> 4) & 1) * 8 + (lane & 7);
    const int bKh   = (lane >> 3) & 1;
    const int swz   = lane & 7;

    for (int c = 0; c < nch; c++) {
        int s = cstage;
        MBAR_WAIT(mb + s * 8, cphase);
        cstage++; if (cstage == 3) { cstage = 0; cphase ^= 1; }

        uint32_t st = sb + (uint32_t)s * STAGE_B;
        #pragma unroll
        for (int ks = 0; ks < 4; ks++) {
            uint32_t afr[4][4];
            #pragma unroll
            for (int mt = 0; mt < 4; mt++) {
                uint32_t roff = (uint32_t)(aRow0 + mt * 16) * 128
                              + (uint32_t)(((ks * 2 + aKh) ^ swz) << 4);
                ldsm4(afr[mt], st + roff);
            }
            uint32_t b1fr[4][2], b2fr[4][2];
            #pragma unroll
            for (int p = 0; p < 2; p++) {
                uint32_t roff = (uint32_t)(bRow0 + p * 16) * 128
                              + (uint32_t)(((ks * 2 + bKh) ^ swz) << 4);
                uint32_t t4[4];
                ldsm4(t4, st + 16384u + roff);
                b1fr[2 * p][0] = t4[0]; b1fr[2 * p][1] = t4[1];
                b1fr[2 * p + 1][0] = t4[2]; b1fr[2 * p + 1][1] = t4[3];
                ldsm4(t4, st + 24576u + roff);
                b2fr[2 * p][0] = t4[0]; b2fr[2 * p][1] = t4[1];
                b2fr[2 * p + 1][0] = t4[2]; b2fr[2 * p + 1][1] = t4[3];
            }
            #pragma unroll
            for (int mt = 0; mt < 4; mt++)
                #pragma unroll
                for (int nt = 0; nt < 4; nt++)
                    mma_f16(acc1[mt][nt], afr[mt], b1fr[nt][0], b1fr[nt][1]);
            #pragma unroll
            for (int mt = 0; mt < 4; mt++)
                #pragma unroll
                for (int nt = 0; nt < 4; nt++)
                    mma_f16(acc2[mt][nt], afr[mt], b2fr[nt][0], b2fr[nt][1]);
        }

        if (lane == 0) MBAR_ARRIVE(mb + 24 + s * 8);

        if (c + 3 < nch) {
            MBAR_WAIT(mb + 24 + pstage * 8, pphase);
            issue(c + 3, pstage);
            CP_MBAR_ARRIVE(mb + pstage * 8);
            pstage++; if (pstage == 3) { pstage = 0; pphase ^= 1; }
        }
    }

    #pragma unroll
    for (int mt = 0; mt < 4; mt++) {
        #pragma unroll
        for (int nt = 0; nt < 4; nt++) {
            int col = colBlock + warp_n * 32 + nt * 8 + (lane & 3) * 2;
            #pragma unroll
            for (int half = 0; half < 2; half++) {
                int row = rowBlock + warp_m * 64 + mt * 16 + (lane >> 2) + half * 8;
                size_t idx = (size_t)row * M + col;
                float t10 = acc1[mt][nt][half * 2 + 0], t20 = acc2[mt][nt][half * 2 + 0];
                float t11 = acc1[mt][nt][half * 2 + 1], t21 = acc2[mt][nt][half * 2 + 1];
                if (FUSE_SILU) {
                    float f0 = t10 * fast_sig(t10) * t20;
                    float f1 = t11 * fast_sig(t11) * t21;
                    *reinterpret_cast<uint32_t*>(C1 + idx) =
                        pack_h2(__float2half(f0), __float2half(f1));
                } else {
                    *reinterpret_cast<uint32_t*>(C1 + idx) =
                        pack_h2(__float2half(t10), __float2half(t11));
                    *reinterpret_cast<uint32_t*>(C2 + idx) =
                        pack_h2(__float2half(fast_sig(t20)), __float2half(fast_sig(t21)));
                }
            }
        }
    }
}

// ---------------------------------------------------------------------------
// Parallel Hawk scan, recompute style ('a' is f16)
// ---------------------------------------------------------------------------
__global__ __launch_bounds__(256) void scan_part1(
    const f16* __restrict__ xin, const f16* __restrict__ a,
    float* __restrict__ csum)
{
    int id = blockIdx.x * 256 + threadIdx.x;
    int chunk = id >> 13;
    int chp = id & (NCHAN - 1);
    int b = chp >> 11;
    int d = chp & (DREC - 1);
    size_t base = ((size_t)b * TLEN + (size_t)chunk * SCHUNK) * DREC + d;

    float h = 0.0f, Aacc = 1.0f;
    #pragma unroll 4
    for (int t = 0; t < SCHUNK; t++) {
        size_t idx = base + (size_t)t * DREC;
        float at = __half2float(__ldg(&a[idx]));
        float xt = __half2float(__ldg(&xin[idx]));
        float s = sqrtf(fmaf(-at, at, 1.0f) + 1e-8f);
        h = fmaf(at, h, s * xt);
        Aacc *= at;
    }
    csum[(size_t)chunk * NCHAN + chp] = Aacc;
    csum[(size_t)NCHUNKS * NCHAN + (size_t)chunk * NCHAN + chp] = h;
}

__global__ __launch_bounds__(256) void scan_part2(
    const float* __restrict__ csum, float* __restrict__ carry)
{
    int chp = blockIdx.x * 256 + threadIdx.x;
    float h = 0.0f;
    #pragma unroll
    for (int c = 0; c < NCHUNKS; c++) {
        carry[(size_t)c * NCHAN + chp] = h;
        float Ac = __ldg(&csum[(size_t)c * NCHAN + chp]);
        float hc = __ldg(&csum[(size_t)NCHUNKS * NCHAN + (size_t)c * NCHAN + chp]);
        h = fmaf(Ac, h, hc);
    }
}

__global__ __launch_bounds__(256) void scan_part3(
    const f16* __restrict__ xin, const f16* __restrict__ a,
    const f16* __restrict__ gate, const float* __restrict__ carry,
    f16* __restrict__ y)
{
    int id = blockIdx.x * 256 + threadIdx.x;
    int chunk = id >> 13;
    int chp = id & (NCHAN - 1);
    int b = chp >> 11;
    int d = chp & (DREC - 1);
    size_t base = ((size_t)b * TLEN + (size_t)chunk * SCHUNK) * DREC + d;

    float h = __ldg(&carry[(size_t)chunk * NCHAN + chp]);
    #pragma unroll 4
    for (int t = 0; t < SCHUNK; t++) {
        size_t idx = base + (size_t)t * DREC;
        float at = __half2float(__ldg(&a[idx]));
        float xt = __half2float(__ldg(&xin[idx]));
        float gt = __half2float(__ldg(&gate[idx]));
        float s = sqrtf(fmaf(-at, at, 1.0f) + 1e-8f);
        h = fmaf(at, h, s * xt);
        y[idx] = __float2half(gt * h);
    }
}

// ---------------------------------------------------------------------------
// Launch
// ---------------------------------------------------------------------------
#define SYM(p, s) cudaGetSymbolAddress((void**)&p, s)

extern "C" void kernel_launch(void* const* d_in, const int* in_sizes, int n_in,
                              void* d_out, int out_size)
{
    const float* x       = (const float*)d_in[0];
    const float* ln1_w   = (const float*)d_in[1];
    const float* ln2_w   = (const float*)d_in[2];
    const float* w_in    = (const float*)d_in[3];
    const float* w_gate  = (const float*)d_in[4];
    const float* a_param = (const float*)d_in[5];
    const float* w_a     = (const float*)d_in[6];
    const float* w_out   = (const float*)d_in[7];
    const float* w_mg    = (const float*)d_in[8];
    const float* w_mu    = (const float*)d_in[9];
    const float* w_md    = (const float*)d_in[10];
    float* out = (float*)d_out;

    f16 *hh, *h2h, *xinh, *gateh, *ah, *yh, *muh, *xresh;
    float *csum, *carry;
    f16 *wi, *wg, *wa, *wo, *wmgp, *wmup, *wmdp;

    SYM(hh, g_h);     SYM(h2h, g_h2);
    SYM(xinh, g_xin); SYM(gateh, g_gate); SYM(ah, g_a);
    SYM(yh, g_y);     SYM(muh, g_mu);     SYM(xresh, g_xres);
    SYM(csum, g_csum); SYM(carry, g_carry);
    SYM(wi, g_wi);  SYM(wg, g_wg);  SYM(wa, g_wa);  SYM(wo, g_wo);
    SYM(wmgp, g_wmg); SYM(wmup, g_wmu); SYM(wmdp, g_wmd);

    cudaFuncSetAttribute(mma_gemm<EPI_BIAS_SIGMOID, true>,  cudaFuncAttributeMaxDynamicSharedMemorySize, GEMM_SMEM);
    cudaFuncSetAttribute(mma_gemm<EPI_RESADD_F32, true>,    cudaFuncAttributeMaxDynamicSharedMemorySize, GEMM_SMEM);
    cudaFuncSetAttribute(mma_gemm<EPI_RESADD_F16, false>,   cudaFuncAttributeMaxDynamicSharedMemorySize, GEMM_SMEM);
    cudaFuncSetAttribute(mma_gemm_dual<0>,                  cudaFuncAttributeMaxDynamicSharedMemorySize, GEMM_SMEM);
    cudaFuncSetAttribute(mma_gemm_dual<1>,                  cudaFuncAttributeMaxDynamicSharedMemorySize, GEMM_SMEM);

    dim3 blk(256);
    dim3 gblk(128);
    const int GY = NTOK / 128;   // 128

    const int n_ih = DREC * HIDDEN / 4;   // 524288
    const int n_aa = DREC * DREC / 4;     // 1048576
    const int n_mh = INTER * HIDDEN / 4;  // 1048576

    // convert all 7 weights to fp16
    {
        int total = 3 * n_ih + n_aa + 3 * n_mh;
        conv7<<<(total + 255) / 256, blk>>>(
            w_in, wi, n_ih,
            w_gate, wg, n_ih,
            w_a, wa, n_aa,
            w_out, wo, n_ih,
            w_mg, wmgp, n_mh,
            w_mu, wmup, n_mh,
            w_md, wmdp, n_mh);
    }

    // h = rmsnorm(x, ln1)
    rmsnorm_h16<false><<<NTOK, blk>>>(x, ln1_w, hh);

    // fused: xin = h@Wi^T, gate = sigmoid(h@Wg^T)
    mma_gemm_dual<0><<<dim3(DREC / 64, GY), gblk, GEMM_SMEM>>>(
        hh, wi, wg, xinh, gateh, DREC, HIDDEN);

    // a = sigmoid(a_param + xin @ w_a^T)  (f16)
    mma_gemm<EPI_BIAS_SIGMOID, true><<<dim3(DREC / 128, GY), gblk, GEMM_SMEM>>>(
        xinh, wa, nullptr, ah, a_param, nullptr, DREC, DREC);

    // scan
    scan_part1<<<(NCHUNKS * NCHAN) / 256, blk>>>(xinh, ah, csum);
    scan_part2<<<NCHAN / 256, blk>>>(csum, carry);
    scan_part3<<<(NCHUNKS * NCHAN) / 256, blk>>>(xinh, ah, gateh, carry, yh);

    // xres = x + y @ w_out^T  (f16 out, f32 aux)
    mma_gemm<EPI_RESADD_F32, true><<<dim3(HIDDEN / 128, GY), gblk, GEMM_SMEM>>>(
        yh, wo, nullptr, xresh, x, nullptr, HIDDEN, DREC);

    // h2 = rmsnorm(xres, ln2)  (f16 in)
    rmsnorm_h16<true><<<NTOK, blk>>>(xresh, ln2_w, h2h);

    // fused MLP gate+up: mu = silu(h2@Wg^T) * (h2@Wu^T)
    mma_gemm_dual<1><<<dim3(INTER / 64, GY), gblk, GEMM_SMEM>>>(
        h2h, wmgp, wmup, muh, nullptr, INTER, HIDDEN);

    // out = xres + mu @ w_mlp_down^T  (f32 out, f16 aux)
    mma_gemm<EPI_RESADD_F16, false><<<dim3(HIDDEN / 128, GY), gblk, GEMM_SMEM>>>(
        muh, wmdp, out, nullptr, nullptr, xresh, HIDDEN, INTER);
}

// round 15
// speedup vs baseline: 1.5953x; 1.0622x over previous
#include <cuda_runtime.h>
#include <cuda_fp16.h>
#include <math.h>
#include <stdint.h>

// ---------------------------------------------------------------------------
// HawkBlock: fp16 mma.sync GEMMs, f32 accum, 3-stage mbarrier ring.
// Dual-B fusions: (w_in + w_gate) and (mlp gate + up -> silu fused).
// NEW: a-path composed — Wcomb = Wa@Wi precomputed (tiny GEMM), so
//      a = sigmoid(ap + h @ Wcomb^T) runs at K=1024 instead of K=2048.
// Fast-math epilogues, f16 'a' + f16 xres, recompute-style parallel scan.
// ---------------------------------------------------------------------------

#define NTOK   16384
#define HIDDEN 1024
#define DREC   2048
#define INTER  4096
#define TLEN   4096
#define NB     4

#define SCHUNK   64
#define NCHUNKS  (TLEN / SCHUNK)   // 64
#define NCHAN    (NB * DREC)       // 8192

typedef __half f16;

// ---- static scratch ----
__device__ f16   g_h   [(size_t)NTOK * HIDDEN];
__device__ f16   g_h2  [(size_t)NTOK * HIDDEN];
__device__ f16   g_xres[(size_t)NTOK * HIDDEN];
__device__ f16   g_xin [(size_t)NTOK * DREC];
__device__ f16   g_gate[(size_t)NTOK * DREC];
__device__ f16   g_a   [(size_t)NTOK * DREC];
__device__ f16   g_y   [(size_t)NTOK * DREC];
__device__ f16   g_mu  [(size_t)NTOK * INTER];
__device__ float g_csum [2 * NCHUNKS * NCHAN];
__device__ float g_carry[NCHUNKS * NCHAN];

// ---- fp16 weights ----
__device__ f16 g_wi   [(size_t)DREC * HIDDEN];
__device__ f16 g_wiT  [(size_t)HIDDEN * DREC];   // w_in transposed
__device__ f16 g_wg   [(size_t)DREC * HIDDEN];
__device__ f16 g_wa   [(size_t)DREC * DREC];
__device__ f16 g_wcomb[(size_t)DREC * HIDDEN];   // Wa @ Wi
__device__ f16 g_wo   [(size_t)HIDDEN * DREC];
__device__ f16 g_wmg  [(size_t)INTER * HIDDEN];
__device__ f16 g_wmu  [(size_t)INTER * HIDDEN];
__device__ f16 g_wmd  [(size_t)HIDDEN * INTER];

// ---------------------------------------------------------------------------
// helpers
// ---------------------------------------------------------------------------
__device__ __forceinline__ uint32_t smem_u32(const void* p) {
    uint32_t a;
    asm("{ .reg .u64 t; cvta.to.shared.u64 t, %1; cvt.u32.u64 %0, t; }"
        : "=r"(a) : "l"(p));
    return a;
}
__device__ __forceinline__ void cp16(uint32_t dst, const void* src) {
    asm volatile("cp.async.cg.shared.global [%0], [%1], 16;"
                 :: "r"(dst), "l"(src));
}
__device__ __forceinline__ void ldsm4(uint32_t (&r)[4], uint32_t addr) {
    asm volatile("ldmatrix.sync.aligned.m8n8.x4.shared.b16 {%0,%1,%2,%3}, [%4];"
                 : "=r"(r[0]), "=r"(r[1]), "=r"(r[2]), "=r"(r[3]) : "r"(addr));
}
__device__ __forceinline__ void mma_f16(float (&d)[4], const uint32_t (&a)[4],
                                        uint32_t b0, uint32_t b1) {
    asm volatile("mma.sync.aligned.m16n8k16.row.col.f32.f16.f16.f32 "
                 "{%0,%1,%2,%3}, {%4,%5,%6,%7}, {%8,%9}, {%0,%1,%2,%3};"
                 : "+f"(d[0]), "+f"(d[1]), "+f"(d[2]), "+f"(d[3])
                 : "r"(a[0]), "r"(a[1]), "r"(a[2]), "r"(a[3]), "r"(b0), "r"(b1));
}
__device__ __forceinline__ uint32_t pack_h2(f16 a, f16 b) {
    __half2 t = __halves2half2(a, b);
    return *reinterpret_cast<uint32_t*>(&t);
}
__device__ __forceinline__ float fast_sig(float v) {
    return __fdividef(1.0f, 1.0f + __expf(-v));
}

// ---- mbarrier primitives ----
#define MBAR_INIT(addr, cnt) \
    asm volatile("mbarrier.init.shared.b64 [%0], %1;" \
                 :: "r"((uint32_t)(addr)), "r"((uint32_t)(cnt)) : "memory")
#define MBAR_ARRIVE(addr) \
    asm volatile("mbarrier.arrive.shared.b64 _, [%0];" \
                 :: "r"((uint32_t)(addr)) : "memory")
#define CP_MBAR_ARRIVE(addr) \
    asm volatile("cp.async.mbarrier.arrive.noinc.shared.b64 [%0];" \
                 :: "r"((uint32_t)(addr)) : "memory")
#define MBAR_WAIT(addr, parity) do {                                            \
    uint32_t _m = (uint32_t)(addr); uint32_t _p = (uint32_t)(parity);           \
    uint32_t _d;                                                                \
    asm volatile("{\n\t.reg .pred p;\n\t"                                       \
        "mbarrier.try_wait.parity.acquire.cta.shared::cta.b64 p, [%1], %2;\n\t" \
        "selp.b32 %0, 1, 0, p;\n\t}" : "=r"(_d) : "r"(_m), "r"(_p) : "memory"); \
    if (!_d) {                                                                  \
        asm volatile("{\n\t.reg .pred P1;\n\t"                                  \
            "W_%=:\n\t"                                                         \
            "mbarrier.try_wait.parity.acquire.cta.shared::cta.b64 P1, [%0], %1, 0x989680;\n\t" \
            "@P1 bra.uni D_%=;\n\t"                                             \
            "bra.uni W_%=;\n\t"                                                 \
            "D_%=:\n\t}" :: "r"(_m), "r"(_p) : "memory");                       \
    }                                                                           \
} while (0)

// ---------------------------------------------------------------------------
// batched weight convert fp32 -> fp16 (7 arrays, one launch)
// ---------------------------------------------------------------------------
__global__ __launch_bounds__(256) void conv7(
    const float* __restrict__ s0, f16* __restrict__ d0, int n0,
    const float* __restrict__ s1, f16* __restrict__ d1, int n1,
    const float* __restrict__ s2, f16* __restrict__ d2, int n2,
    const float* __restrict__ s3, f16* __restrict__ d3, int n3,
    const float* __restrict__ s4, f16* __restrict__ d4, int n4,
    const float* __restrict__ s5, f16* __restrict__ d5, int n5,
    const float* __restrict__ s6, f16* __restrict__ d6, int n6)
{
    int j = blockIdx.x * 256 + threadIdx.x;
    const float* s; f16* d;
    if (j < n0) { s = s0; d = d0; }
    else { j -= n0;
    if (j < n1) { s = s1; d = d1; }
    else { j -= n1;
    if (j < n2) { s = s2; d = d2; }
    else { j -= n2;
    if (j < n3) { s = s3; d = d3; }
    else { j -= n3;
    if (j < n4) { s = s4; d = d4; }
    else { j -= n4;
    if (j < n5) { s = s5; d = d5; }
    else { j -= n5;
    if (j >= n6) return;
    s = s6; d = d6; }}}}}}
    float4 v = reinterpret_cast<const float4*>(s)[j];
    reinterpret_cast<uint2*>(d)[j] = make_uint2(
        pack_h2(__float2half(v.x), __float2half(v.y)),
        pack_h2(__float2half(v.z), __float2half(v.w)));
}

// ---------------------------------------------------------------------------
// f16 transpose: out[c][r] = in[r][c].  in: [R, C], out: [C, R].
// ---------------------------------------------------------------------------
__global__ __launch_bounds__(256) void transpose_h16(
    const f16* __restrict__ in, f16* __restrict__ out, int R, int C)
{
    __shared__ f16 tile[32][33];
    int tx = threadIdx.x & 31;
    int ty = threadIdx.x >> 5;       // 0..7
    int c0 = blockIdx.x * 32;
    int r0 = blockIdx.y * 32;
    #pragma unroll
    for (int i = 0; i < 32; i += 8)
        tile[ty + i][tx] = in[(size_t)(r0 + ty + i) * C + c0 + tx];
    __syncthreads();
    #pragma unroll
    for (int i = 0; i < 32; i += 8)
        out[(size_t)(c0 + ty + i) * R + r0 + tx] = tile[tx][ty + i];
}

// ---------------------------------------------------------------------------
// RMSNorm -> fp16.  IN16: input array is f16 (xres), else f32.
// ---------------------------------------------------------------------------
template<bool IN16>
__global__ __launch_bounds__(256) void rmsnorm_h16(
    const void* __restrict__ xin, const float* __restrict__ w,
    f16* __restrict__ o)
{
    int tkn = blockIdx.x;
    int t = threadIdx.x;
    float f[4];
    if (IN16) {
        const f16* xp = (const f16*)xin;
        uint2 u = reinterpret_cast<const uint2*>(xp + (size_t)tkn * HIDDEN)[t];
        __half2 p0 = *reinterpret_cast<__half2*>(&u.x);
        __half2 p1 = *reinterpret_cast<__half2*>(&u.y);
        f[0] = __low2float(p0); f[1] = __high2float(p0);
        f[2] = __low2float(p1); f[3] = __high2float(p1);
    } else {
        float4 v = reinterpret_cast<const float4*>((const float*)xin + (size_t)tkn * HIDDEN)[t];
        f[0] = v.x; f[1] = v.y; f[2] = v.z; f[3] = v.w;
    }
    float s = f[0]*f[0] + f[1]*f[1] + f[2]*f[2] + f[3]*f[3];
    #pragma unroll
    for (int o2 = 16; o2 > 0; o2 >>= 1) s += __shfl_xor_sync(0xFFFFFFFFu, s, o2);
    __shared__ float ws[8];
    __shared__ float tot_sh;
    if ((t & 31) == 0) ws[t >> 5] = s;
    __syncthreads();
    if (t < 32) {
        float z = (t < 8) ? ws[t] : 0.0f;
        #pragma unroll
        for (int o2 = 4; o2 > 0; o2 >>= 1) z += __shfl_xor_sync(0xFFFFFFFFu, z, o2);
        if (t == 0) tot_sh = z;
    }
    __syncthreads();
    float r = rsqrtf(tot_sh * (1.0f / HIDDEN) + 1e-6f);
    float4 wv = reinterpret_cast<const float4*>(w)[t];
    size_t q = (size_t)tkn * (HIDDEN / 4) + t;
    reinterpret_cast<uint2*>(o)[q] = make_uint2(
        pack_h2(__float2half(f[0] * r * wv.x), __float2half(f[1] * r * wv.y)),
        pack_h2(__float2half(f[2] * r * wv.z), __float2half(f[3] * r * wv.w)));
}

// ---------------------------------------------------------------------------
// Single-B GEMM (CTA 128x128, 4 warps @ 64x64, 3-stage mbarrier ring)
// ---------------------------------------------------------------------------
#define EPI_NONE          0
#define EPI_BIAS_SIGMOID  2
#define EPI_RESADD_F32    3   // aux f32 array
#define EPI_RESADD_F16    4   // aux f16 array

template<int EPI>
__device__ __forceinline__ float epi_apply(float v,
                                           const float* __restrict__ auxf,
                                           const f16* __restrict__ auxh,
                                           size_t idx, int col)
{
    if (EPI == EPI_BIAS_SIGMOID) return fast_sig(v + __ldg(&auxf[col]));
    if (EPI == EPI_RESADD_F32)   return v + __ldg(&auxf[idx]);
    if (EPI == EPI_RESADD_F16)   return v + __half2float(__ldg(&auxh[idx]));
    return v;
}

#define STAGE_B   32768u
#define GEMM_SMEM (3 * 32768 + 64)

template<int EPI, bool OUT16>
__global__ __launch_bounds__(128, 2) void mma_gemm(
    const f16* __restrict__ A, const f16* __restrict__ B,
    float* __restrict__ Cf, f16* __restrict__ Ch,
    const float* __restrict__ auxf, const f16* __restrict__ auxh,
    int M, int K)
{
    extern __shared__ char smem[];
    const uint32_t sb = smem_u32(smem);
    const uint32_t mb = sb + 3u * STAGE_B;
    const int tid = threadIdx.x;
    const int lane = tid & 31;
    const int wid = tid >> 5;
    const int warp_m = wid >> 1;
    const int warp_n = wid & 1;
    const int rowBlock = blockIdx.y * 128;
    const int colBlock = blockIdx.x * 128;
    const int nch = K >> 6;

    const f16* gpA = A + (size_t)rowBlock * K;
    const f16* gpB = B + (size_t)colBlock * K;

    if (tid == 0) {
        #pragma unroll
        for (int s = 0; s < 3; s++) {
            MBAR_INIT(mb + s * 8, 128);
            MBAR_INIT(mb + 24 + s * 8, 4);
        }
    }
    __syncthreads();

    auto issue = [&](int c, int buf) {
        const int kb = c * 64;
        uint32_t st = sb + (uint32_t)buf * STAGE_B;
        #pragma unroll
        for (int i = 0; i < 8; i++) {
            int u = tid + i * 128;
            int r = u >> 3, cc = u & 7;
            cp16(st + r * 128 + ((cc ^ (r & 7)) << 4),
                 gpA + (size_t)r * K + kb + cc * 8);
        }
        #pragma unroll
        for (int i = 0; i < 8; i++) {
            int u = tid + i * 128;
            int r = u >> 3, cc = u & 7;
            cp16(st + 16384u + r * 128 + ((cc ^ (r & 7)) << 4),
                 gpB + (size_t)r * K + kb + cc * 8);
        }
    };

    float acc[4][8][4];
    #pragma unroll
    for (int i = 0; i < 4; i++)
        #pragma unroll
        for (int j = 0; j < 8; j++)
            #pragma unroll
            for (int k = 0; k < 4; k++) acc[i][j][k] = 0.0f;

    int pstage = 0, pphase = 1;
    int cstage = 0, cphase = 0;

    #pragma unroll
    for (int s = 0; s < 3; s++) {
        if (s < nch) {
            MBAR_WAIT(mb + 24 + pstage * 8, pphase);
            issue(s, pstage);
            CP_MBAR_ARRIVE(mb + pstage * 8);
            pstage++; if (pstage == 3) { pstage = 0; pphase ^= 1; }
        }
    }

    const int aRow0 = warp_m * 64 + (lane & 7) + ((lane >> 3) & 1) * 8;
    const int aKh   = (lane >> 4) & 1;
    const int bRow0 = warp_n * 64 + ((lane >> 4) & 1) * 8 + (lane & 7);
    const int bKh   = (lane >> 3) & 1;
    const int swz   = lane & 7;

    for (int c = 0; c < nch; c++) {
        int s = cstage;
        MBAR_WAIT(mb + s * 8, cphase);
        cstage++; if (cstage == 3) { cstage = 0; cphase ^= 1; }

        uint32_t st = sb + (uint32_t)s * STAGE_B;
        #pragma unroll
        for (int ks = 0; ks < 4; ks++) {
            uint32_t afr[4][4];
            #pragma unroll
            for (int mt = 0; mt < 4; mt++) {
                uint32_t roff = (uint32_t)(aRow0 + mt * 16) * 128
                              + (uint32_t)(((ks * 2 + aKh) ^ swz) << 4);
                ldsm4(afr[mt], st + roff);
            }
            uint32_t bfr[8][2];
            #pragma unroll
            for (int p = 0; p < 4; p++) {
                uint32_t roff = (uint32_t)(bRow0 + p * 16) * 128
                              + (uint32_t)(((ks * 2 + bKh) ^ swz) << 4);
                uint32_t t4[4];
                ldsm4(t4, st + 16384u + roff);
                bfr[2 * p][0] = t4[0]; bfr[2 * p][1] = t4[1];
                bfr[2 * p + 1][0] = t4[2]; bfr[2 * p + 1][1] = t4[3];
            }
            #pragma unroll
            for (int mt = 0; mt < 4; mt++)
                #pragma unroll
                for (int nt = 0; nt < 8; nt++)
                    mma_f16(acc[mt][nt], afr[mt], bfr[nt][0], bfr[nt][1]);
        }

        if (lane == 0) MBAR_ARRIVE(mb + 24 + s * 8);

        if (c + 3 < nch) {
            MBAR_WAIT(mb + 24 + pstage * 8, pphase);
            issue(c + 3, pstage);
            CP_MBAR_ARRIVE(mb + pstage * 8);
            pstage++; if (pstage == 3) { pstage = 0; pphase ^= 1; }
        }
    }

    #pragma unroll
    for (int mt = 0; mt < 4; mt++) {
        #pragma unroll
        for (int nt = 0; nt < 8; nt++) {
            int col = colBlock + warp_n * 64 + nt * 8 + (lane & 3) * 2;
            #pragma unroll
            for (int half = 0; half < 2; half++) {
                int row = rowBlock + warp_m * 64 + mt * 16 + (lane >> 2) + half * 8;
                size_t idx = (size_t)row * M + col;
                float f0 = epi_apply<EPI>(acc[mt][nt][half * 2 + 0], auxf, auxh, idx, col);
                float f1 = epi_apply<EPI>(acc[mt][nt][half * 2 + 1], auxf, auxh, idx + 1, col + 1);
                if (OUT16) {
                    *reinterpret_cast<uint32_t*>(Ch + idx) =
                        pack_h2(__float2half(f0), __float2half(f1));
                } else {
                    *reinterpret_cast<float2*>(Cf + idx) = make_float2(f0, f1);
                }
            }
        }
    }
}

// ---------------------------------------------------------------------------
// Dual-B GEMM: T1 = A@B1^T, T2 = A@B2^T on one A pass.
// FUSE_SILU=1: C1 = silu(T1)*T2        (MLP gate+up)
// FUSE_SILU=0: C1 = T1, C2 = sigmoid(T2) (w_in + w_gate)
// ---------------------------------------------------------------------------
template<int FUSE_SILU>
__global__ __launch_bounds__(128, 2) void mma_gemm_dual(
    const f16* __restrict__ A, const f16* __restrict__ B1,
    const f16* __restrict__ B2, f16* __restrict__ C1, f16* __restrict__ C2,
    int M, int K)
{
    extern __shared__ char smem[];
    const uint32_t sb = smem_u32(smem);
    const uint32_t mb = sb + 3u * STAGE_B;
    const int tid = threadIdx.x;
    const int lane = tid & 31;
    const int wid = tid >> 5;
    const int warp_m = wid >> 1;
    const int warp_n = wid & 1;
    const int rowBlock = blockIdx.y * 128;
    const int colBlock = blockIdx.x * 64;
    const int nch = K >> 6;

    const f16* gpA  = A  + (size_t)rowBlock * K;
    const f16* gpB1 = B1 + (size_t)colBlock * K;
    const f16* gpB2 = B2 + (size_t)colBlock * K;

    if (tid == 0) {
        #pragma unroll
        for (int s = 0; s < 3; s++) {
            MBAR_INIT(mb + s * 8, 128);
            MBAR_INIT(mb + 24 + s * 8, 4);
        }
    }
    __syncthreads();

    auto issue = [&](int c, int buf) {
        const int kb = c * 64;
        uint32_t st = sb + (uint32_t)buf * STAGE_B;
        #pragma unroll
        for (int i = 0; i < 8; i++) {
            int u = tid + i * 128;
            int r = u >> 3, cc = u & 7;
            cp16(st + r * 128 + ((cc ^ (r & 7)) << 4),
                 gpA + (size_t)r * K + kb + cc * 8);
        }
        #pragma unroll
        for (int i = 0; i < 4; i++) {
            int u = tid + i * 128;
            int r = u >> 3, cc = u & 7;
            cp16(st + 16384u + r * 128 + ((cc ^ (r & 7)) << 4),
                 gpB1 + (size_t)r * K + kb + cc * 8);
        }
        #pragma unroll
        for (int i = 0; i < 4; i++) {
            int u = tid + i * 128;
            int r = u >> 3, cc = u & 7;
            cp16(st + 24576u + r * 128 + ((cc ^ (r & 7)) << 4),
                 gpB2 + (size_t)r * K + kb + cc * 8);
        }
    };

    float acc1[4][4][4], acc2[4][4][4];
    #pragma unroll
    for (int i = 0; i < 4; i++)
        #pragma unroll
        for (int j = 0; j < 4; j++)
            #pragma unroll
            for (int k = 0; k < 4; k++) { acc1[i][j][k] = 0.0f; acc2[i][j][k] = 0.0f; }

    int pstage = 0, pphase = 1;
    int cstage = 0, cphase = 0;

    #pragma unroll
    for (int s = 0; s < 3; s++) {
        if (s < nch) {
            MBAR_WAIT(mb + 24 + pstage * 8, pphase);
            issue(s, pstage);
            CP_MBAR_ARRIVE(mb + pstage * 8);
            pstage++; if (pstage == 3) { pstage = 0; pphase ^= 1; }
        }
    }

    const int aRow0 = warp_m * 64 + (lane & 7) + ((lane >> 3) & 1) * 8;
    const int aKh   = (lane >> 4) & 1;
    const int bRow0 = warp_n * 32 + ((lane >> 4) & 1) * 8 + (lane & 7);
    const int bKh   = (lane >> 3) & 1;
    const int swz   = lane & 7;

    for (int c = 0; c < nch; c++) {
        int s = cstage;
        MBAR_WAIT(mb + s * 8, cphase);
        cstage++; if (cstage == 3) { cstage = 0; cphase ^= 1; }

        uint32_t st = sb + (uint32_t)s * STAGE_B;
        #pragma unroll
        for (int ks = 0; ks < 4; ks++) {
            uint32_t afr[4][4];
            #pragma unroll
            for (int mt = 0; mt < 4; mt++) {
                uint32_t roff = (uint32_t)(aRow0 + mt * 16) * 128
                              + (uint32_t)(((ks * 2 + aKh) ^ swz) << 4);
                ldsm4(afr[mt], st + roff);
            }
            uint32_t b1fr[4][2], b2fr[4][2];
            #pragma unroll
            for (int p = 0; p < 2; p++) {
                uint32_t roff = (uint32_t)(bRow0 + p * 16) * 128
                              + (uint32_t)(((ks * 2 + bKh) ^ swz) << 4);
                uint32_t t4[4];
                ldsm4(t4, st + 16384u + roff);
                b1fr[2 * p][0] = t4[0]; b1fr[2 * p][1] = t4[1];
                b1fr[2 * p + 1][0] = t4[2]; b1fr[2 * p + 1][1] = t4[3];
                ldsm4(t4, st + 24576u + roff);
                b2fr[2 * p][0] = t4[0]; b2fr[2 * p][1] = t4[1];
                b2fr[2 * p + 1][0] = t4[2]; b2fr[2 * p + 1][1] = t4[3];
            }
            #pragma unroll
            for (int mt = 0; mt < 4; mt++)
                #pragma unroll
                for (int nt = 0; nt < 4; nt++)
                    mma_f16(acc1[mt][nt], afr[mt], b1fr[nt][0], b1fr[nt][1]);
            #pragma unroll
            for (int mt = 0; mt < 4; mt++)
                #pragma unroll
                for (int nt = 0; nt < 4; nt++)
                    mma_f16(acc2[mt][nt], afr[mt], b2fr[nt][0], b2fr[nt][1]);
        }

        if (lane == 0) MBAR_ARRIVE(mb + 24 + s * 8);

        if (c + 3 < nch) {
            MBAR_WAIT(mb + 24 + pstage * 8, pphase);
            issue(c + 3, pstage);
            CP_MBAR_ARRIVE(mb + pstage * 8);
            pstage++; if (pstage == 3) { pstage = 0; pphase ^= 1; }
        }
    }

    #pragma unroll
    for (int mt = 0; mt < 4; mt++) {
        #pragma unroll
        for (int nt = 0; nt < 4; nt++) {
            int col = colBlock + warp_n * 32 + nt * 8 + (lane & 3) * 2;
            #pragma unroll
            for (int half = 0; half < 2; half++) {
                int row = rowBlock + warp_m * 64 + mt * 16 + (lane >> 2) + half * 8;
                size_t idx = (size_t)row * M + col;
                float t10 = acc1[mt][nt][half * 2 + 0], t20 = acc2[mt][nt][half * 2 + 0];
                float t11 = acc1[mt][nt][half * 2 + 1], t21 = acc2[mt][nt][half * 2 + 1];
                if (FUSE_SILU) {
                    float f0 = t10 * fast_sig(t10) * t20;
                    float f1 = t11 * fast_sig(t11) * t21;
                    *reinterpret_cast<uint32_t*>(C1 + idx) =
                        pack_h2(__float2half(f0), __float2half(f1));
                } else {
                    *reinterpret_cast<uint32_t*>(C1 + idx) =
                        pack_h2(__float2half(t10), __float2half(t11));
                    *reinterpret_cast<uint32_t*>(C2 + idx) =
                        pack_h2(__float2half(fast_sig(t20)), __float2half(fast_sig(t21)));
                }
            }
        }
    }
}

// ---------------------------------------------------------------------------
// Parallel Hawk scan, recompute style ('a' is f16)
// ---------------------------------------------------------------------------
__global__ __launch_bounds__(256) void scan_part1(
    const f16* __restrict__ xin, const f16* __restrict__ a,
    float* __restrict__ csum)
{
    int id = blockIdx.x * 256 + threadIdx.x;
    int chunk = id >> 13;
    int chp = id & (NCHAN - 1);
    int b = chp >> 11;
    int d = chp & (DREC - 1);
    size_t base = ((size_t)b * TLEN + (size_t)chunk * SCHUNK) * DREC + d;

    float h = 0.0f, Aacc = 1.0f;
    #pragma unroll 4
    for (int t = 0; t < SCHUNK; t++) {
        size_t idx = base + (size_t)t * DREC;
        float at = __half2float(__ldg(&a[idx]));
        float xt = __half2float(__ldg(&xin[idx]));
        float s = sqrtf(fmaf(-at, at, 1.0f) + 1e-8f);
        h = fmaf(at, h, s * xt);
        Aacc *= at;
    }
    csum[(size_t)chunk * NCHAN + chp] = Aacc;
    csum[(size_t)NCHUNKS * NCHAN + (size_t)chunk * NCHAN + chp] = h;
}

__global__ __launch_bounds__(256) void scan_part2(
    const float* __restrict__ csum, float* __restrict__ carry)
{
    int chp = blockIdx.x * 256 + threadIdx.x;
    float h = 0.0f;
    #pragma unroll
    for (int c = 0; c < NCHUNKS; c++) {
        carry[(size_t)c * NCHAN + chp] = h;
        float Ac = __ldg(&csum[(size_t)c * NCHAN + chp]);
        float hc = __ldg(&csum[(size_t)NCHUNKS * NCHAN + (size_t)c * NCHAN + chp]);
        h = fmaf(Ac, h, hc);
    }
}

__global__ __launch_bounds__(256) void scan_part3(
    const f16* __restrict__ xin, const f16* __restrict__ a,
    const f16* __restrict__ gate, const float* __restrict__ carry,
    f16* __restrict__ y)
{
    int id = blockIdx.x * 256 + threadIdx.x;
    int chunk = id >> 13;
    int chp = id & (NCHAN - 1);
    int b = chp >> 11;
    int d = chp & (DREC - 1);
    size_t base = ((size_t)b * TLEN + (size_t)chunk * SCHUNK) * DREC + d;

    float h = __ldg(&carry[(size_t)chunk * NCHAN + chp]);
    #pragma unroll 4
    for (int t = 0; t < SCHUNK; t++) {
        size_t idx = base + (size_t)t * DREC;
        float at = __half2float(__ldg(&a[idx]));
        float xt = __half2float(__ldg(&xin[idx]));
        float gt = __half2float(__ldg(&gate[idx]));
        float s = sqrtf(fmaf(-at, at, 1.0f) + 1e-8f);
        h = fmaf(at, h, s * xt);
        y[idx] = __float2half(gt * h);
    }
}

// ---------------------------------------------------------------------------
// Launch
// ---------------------------------------------------------------------------
#define SYM(p, s) cudaGetSymbolAddress((void**)&p, s)

extern "C" void kernel_launch(void* const* d_in, const int* in_sizes, int n_in,
                              void* d_out, int out_size)
{
    const float* x       = (const float*)d_in[0];
    const float* ln1_w   = (const float*)d_in[1];
    const float* ln2_w   = (const float*)d_in[2];
    const float* w_in    = (const float*)d_in[3];
    const float* w_gate  = (const float*)d_in[4];
    const float* a_param = (const float*)d_in[5];
    const float* w_a     = (const float*)d_in[6];
    const float* w_out   = (const float*)d_in[7];
    const float* w_mg    = (const float*)d_in[8];
    const float* w_mu    = (const float*)d_in[9];
    const float* w_md    = (const float*)d_in[10];
    float* out = (float*)d_out;

    f16 *hh, *h2h, *xinh, *gateh, *ah, *yh, *muh, *xresh;
    float *csum, *carry;
    f16 *wi, *wiT, *wg, *wa, *wcomb, *wo, *wmgp, *wmup, *wmdp;

    SYM(hh, g_h);     SYM(h2h, g_h2);
    SYM(xinh, g_xin); SYM(gateh, g_gate); SYM(ah, g_a);
    SYM(yh, g_y);     SYM(muh, g_mu);     SYM(xresh, g_xres);
    SYM(csum, g_csum); SYM(carry, g_carry);
    SYM(wi, g_wi);  SYM(wiT, g_wiT);  SYM(wg, g_wg);  SYM(wa, g_wa);
    SYM(wcomb, g_wcomb);  SYM(wo, g_wo);
    SYM(wmgp, g_wmg); SYM(wmup, g_wmu); SYM(wmdp, g_wmd);

    cudaFuncSetAttribute(mma_gemm<EPI_NONE, true>,          cudaFuncAttributeMaxDynamicSharedMemorySize, GEMM_SMEM);
    cudaFuncSetAttribute(mma_gemm<EPI_BIAS_SIGMOID, true>,  cudaFuncAttributeMaxDynamicSharedMemorySize, GEMM_SMEM);
    cudaFuncSetAttribute(mma_gemm<EPI_RESADD_F32, true>,    cudaFuncAttributeMaxDynamicSharedMemorySize, GEMM_SMEM);
    cudaFuncSetAttribute(mma_gemm<EPI_RESADD_F16, false>,   cudaFuncAttributeMaxDynamicSharedMemorySize, GEMM_SMEM);
    cudaFuncSetAttribute(mma_gemm_dual<0>,                  cudaFuncAttributeMaxDynamicSharedMemorySize, GEMM_SMEM);
    cudaFuncSetAttribute(mma_gemm_dual<1>,                  cudaFuncAttributeMaxDynamicSharedMemorySize, GEMM_SMEM);

    dim3 blk(256);
    dim3 gblk(128);
    const int GY = NTOK / 128;   // 128

    const int n_ih = DREC * HIDDEN / 4;   // 524288
    const int n_aa = DREC * DREC / 4;     // 1048576
    const int n_mh = INTER * HIDDEN / 4;  // 1048576

    // convert all 7 weights to fp16
    {
        int total = 3 * n_ih + n_aa + 3 * n_mh;
        conv7<<<(total + 255) / 256, blk>>>(
            w_in, wi, n_ih,
            w_gate, wg, n_ih,
            w_a, wa, n_aa,
            w_out, wo, n_ih,
            w_mg, wmgp, n_mh,
            w_mu, wmup, n_mh,
            w_md, wmdp, n_mh);
    }

    // wiT = wi^T  ([DREC,HIDDEN] -> [HIDDEN,DREC])
    transpose_h16<<<dim3(HIDDEN / 32, DREC / 32), blk>>>(wi, wiT, DREC, HIDDEN);

    // Wcomb = Wa @ Wi  ([DREC,DREC] @ [DREC,HIDDEN] -> [DREC,HIDDEN])
    // via C[N=DREC, M=HIDDEN] = wa[N,K=DREC] @ wiT[M,K=DREC]^T
    mma_gemm<EPI_NONE, true><<<dim3(HIDDEN / 128, DREC / 128), gblk, GEMM_SMEM>>>(
        wa, wiT, nullptr, wcomb, nullptr, nullptr, HIDDEN, DREC);

    // h = rmsnorm(x, ln1)
    rmsnorm_h16<false><<<NTOK, blk>>>(x, ln1_w, hh);

    // fused: xin = h@Wi^T, gate = sigmoid(h@Wg^T)
    mma_gemm_dual<0><<<dim3(DREC / 64, GY), gblk, GEMM_SMEM>>>(
        hh, wi, wg, xinh, gateh, DREC, HIDDEN);

    // a = sigmoid(a_param + h @ Wcomb^T)   (K=1024 — composed path)
    mma_gemm<EPI_BIAS_SIGMOID, true><<<dim3(DREC / 128, GY), gblk, GEMM_SMEM>>>(
        hh, wcomb, nullptr, ah, a_param, nullptr, DREC, HIDDEN);

    // scan
    scan_part1<<<(NCHUNKS * NCHAN) / 256, blk>>>(xinh, ah, csum);
    scan_part2<<<NCHAN / 256, blk>>>(csum, carry);
    scan_part3<<<(NCHUNKS * NCHAN) / 256, blk>>>(xinh, ah, gateh, carry, yh);

    // xres = x + y @ w_out^T  (f16 out, f32 aux)
    mma_gemm<EPI_RESADD_F32, true><<<dim3(HIDDEN / 128, GY), gblk, GEMM_SMEM>>>(
        yh, wo, nullptr, xresh, x, nullptr, HIDDEN, DREC);

    // h2 = rmsnorm(xres, ln2)  (f16 in)
    rmsnorm_h16<true><<<NTOK, blk>>>(xresh, ln2_w, h2h);

    // fused MLP gate+up: mu = silu(h2@Wg^T) * (h2@Wu^T)
    mma_gemm_dual<1><<<dim3(INTER / 64, GY), gblk, GEMM_SMEM>>>(
        h2h, wmgp, wmup, muh, nullptr, INTER, HIDDEN);

    // out = xres + mu @ w_mlp_down^T  (f32 out, f16 aux)
    mma_gemm<EPI_RESADD_F16, false><<<dim3(HIDDEN / 128, GY), gblk, GEMM_SMEM>>>(
        muh, wmdp, out, nullptr, nullptr, xresh, HIDDEN, INTER);
}

// round 16
// speedup vs baseline: 1.6589x; 1.0398x over previous
#include <cuda_runtime.h>
#include <cuda_fp16.h>
#include <math.h>
#include <stdint.h>

// ---------------------------------------------------------------------------
// HawkBlock: fp16 mma.sync GEMMs, f32 accum, 3-stage mbarrier ring.
// Dual-B fusions: (w_in + w_gate) and (mlp gate + up -> silu fused).
// a-path composed: Wcomb = Wa@Wi precomputed, a-GEMM at K=1024.
// Fast-math epilogues, f16 'a'/xres, h2-paired recompute parallel scan.
// ---------------------------------------------------------------------------

#define NTOK   16384
#define HIDDEN 1024
#define DREC   2048
#define INTER  4096
#define TLEN   4096
#define NB     4

#define SCHUNK   64
#define NCHUNKS  (TLEN / SCHUNK)   // 64
#define NCHAN    (NB * DREC)       // 8192

typedef __half f16;

// ---- static scratch ----
__device__ f16   g_h   [(size_t)NTOK * HIDDEN];
__device__ f16   g_h2  [(size_t)NTOK * HIDDEN];
__device__ f16   g_xres[(size_t)NTOK * HIDDEN];
__device__ f16   g_xin [(size_t)NTOK * DREC];
__device__ f16   g_gate[(size_t)NTOK * DREC];
__device__ f16   g_a   [(size_t)NTOK * DREC];
__device__ f16   g_y   [(size_t)NTOK * DREC];
__device__ f16   g_mu  [(size_t)NTOK * INTER];
__device__ float g_csum [2 * NCHUNKS * NCHAN];
__device__ float g_carry[NCHUNKS * NCHAN];

// ---- fp16 weights ----
__device__ f16 g_wi   [(size_t)DREC * HIDDEN];
__device__ f16 g_wiT  [(size_t)HIDDEN * DREC];
__device__ f16 g_wg   [(size_t)DREC * HIDDEN];
__device__ f16 g_wa   [(size_t)DREC * DREC];
__device__ f16 g_wcomb[(size_t)DREC * HIDDEN];
__device__ f16 g_wo   [(size_t)HIDDEN * DREC];
__device__ f16 g_wmg  [(size_t)INTER * HIDDEN];
__device__ f16 g_wmu  [(size_t)INTER * HIDDEN];
__device__ f16 g_wmd  [(size_t)HIDDEN * INTER];

// ---------------------------------------------------------------------------
// helpers
// ---------------------------------------------------------------------------
__device__ __forceinline__ uint32_t smem_u32(const void* p) {
    uint32_t a;
    asm("{ .reg .u64 t; cvta.to.shared.u64 t, %1; cvt.u32.u64 %0, t; }"
        : "=r"(a) : "l"(p));
    return a;
}
__device__ __forceinline__ void cp16(uint32_t dst, const void* src) {
    asm volatile("cp.async.cg.shared.global [%0], [%1], 16;"
                 :: "r"(dst), "l"(src));
}
__device__ __forceinline__ void ldsm4(uint32_t (&r)[4], uint32_t addr) {
    asm volatile("ldmatrix.sync.aligned.m8n8.x4.shared.b16 {%0,%1,%2,%3}, [%4];"
                 : "=r"(r[0]), "=r"(r[1]), "=r"(r[2]), "=r"(r[3]) : "r"(addr));
}
__device__ __forceinline__ void mma_f16(float (&d)[4], const uint32_t (&a)[4],
                                        uint32_t b0, uint32_t b1) {
    asm volatile("mma.sync.aligned.m16n8k16.row.col.f32.f16.f16.f32 "
                 "{%0,%1,%2,%3}, {%4,%5,%6,%7}, {%8,%9}, {%0,%1,%2,%3};"
                 : "+f"(d[0]), "+f"(d[1]), "+f"(d[2]), "+f"(d[3])
                 : "r"(a[0]), "r"(a[1]), "r"(a[2]), "r"(a[3]), "r"(b0), "r"(b1));
}
__device__ __forceinline__ uint32_t pack_h2(f16 a, f16 b) {
    __half2 t = __halves2half2(a, b);
    return *reinterpret_cast<uint32_t*>(&t);
}
__device__ __forceinline__ float fast_sig(float v) {
    return __fdividef(1.0f, 1.0f + __expf(-v));
}

// ---- mbarrier primitives ----
#define MBAR_INIT(addr, cnt) \
    asm volatile("mbarrier.init.shared.b64 [%0], %1;" \
                 :: "r"((uint32_t)(addr)), "r"((uint32_t)(cnt)) : "memory")
#define MBAR_ARRIVE(addr) \
    asm volatile("mbarrier.arrive.shared.b64 _, [%0];" \
                 :: "r"((uint32_t)(addr)) : "memory")
#define CP_MBAR_ARRIVE(addr) \
    asm volatile("cp.async.mbarrier.arrive.noinc.shared.b64 [%0];" \
                 :: "r"((uint32_t)(addr)) : "memory")
#define MBAR_WAIT(addr, parity) do {                                            \
    uint32_t _m = (uint32_t)(addr); uint32_t _p = (uint32_t)(parity);           \
    uint32_t _d;                                                                \
    asm volatile("{\n\t.reg .pred p;\n\t"                                       \
        "mbarrier.try_wait.parity.acquire.cta.shared::cta.b64 p, [%1], %2;\n\t" \
        "selp.b32 %0, 1, 0, p;\n\t}" : "=r"(_d) : "r"(_m), "r"(_p) : "memory"); \
    if (!_d) {                                                                  \
        asm volatile("{\n\t.reg .pred P1;\n\t"                                  \
            "W_%=:\n\t"                                                         \
            "mbarrier.try_wait.parity.acquire.cta.shared::cta.b64 P1, [%0], %1, 0x989680;\n\t" \
            "@P1 bra.uni D_%=;\n\t"                                             \
            "bra.uni W_%=;\n\t"                                                 \
            "D_%=:\n\t}" :: "r"(_m), "r"(_p) : "memory");                       \
    }                                                                           \
} while (0)

// ---------------------------------------------------------------------------
// batched weight convert fp32 -> fp16 (7 arrays, one launch)
// ---------------------------------------------------------------------------
__global__ __launch_bounds__(256) void conv7(
    const float* __restrict__ s0, f16* __restrict__ d0, int n0,
    const float* __restrict__ s1, f16* __restrict__ d1, int n1,
    const float* __restrict__ s2, f16* __restrict__ d2, int n2,
    const float* __restrict__ s3, f16* __restrict__ d3, int n3,
    const float* __restrict__ s4, f16* __restrict__ d4, int n4,
    const float* __restrict__ s5, f16* __restrict__ d5, int n5,
    const float* __restrict__ s6, f16* __restrict__ d6, int n6)
{
    int j = blockIdx.x * 256 + threadIdx.x;
    const float* s; f16* d;
    if (j < n0) { s = s0; d = d0; }
    else { j -= n0;
    if (j < n1) { s = s1; d = d1; }
    else { j -= n1;
    if (j < n2) { s = s2; d = d2; }
    else { j -= n2;
    if (j < n3) { s = s3; d = d3; }
    else { j -= n3;
    if (j < n4) { s = s4; d = d4; }
    else { j -= n4;
    if (j < n5) { s = s5; d = d5; }
    else { j -= n5;
    if (j >= n6) return;
    s = s6; d = d6; }}}}}}
    float4 v = reinterpret_cast<const float4*>(s)[j];
    reinterpret_cast<uint2*>(d)[j] = make_uint2(
        pack_h2(__float2half(v.x), __float2half(v.y)),
        pack_h2(__float2half(v.z), __float2half(v.w)));
}

// ---------------------------------------------------------------------------
// f16 transpose: out[c][r] = in[r][c].  in: [R, C], out: [C, R].
// ---------------------------------------------------------------------------
__global__ __launch_bounds__(256) void transpose_h16(
    const f16* __restrict__ in, f16* __restrict__ out, int R, int C)
{
    __shared__ f16 tile[32][33];
    int tx = threadIdx.x & 31;
    int ty = threadIdx.x >> 5;
    int c0 = blockIdx.x * 32;
    int r0 = blockIdx.y * 32;
    #pragma unroll
    for (int i = 0; i < 32; i += 8)
        tile[ty + i][tx] = in[(size_t)(r0 + ty + i) * C + c0 + tx];
    __syncthreads();
    #pragma unroll
    for (int i = 0; i < 32; i += 8)
        out[(size_t)(c0 + ty + i) * R + r0 + tx] = tile[tx][ty + i];
}

// ---------------------------------------------------------------------------
// RMSNorm -> fp16.  IN16: input array is f16 (xres), else f32.
// ---------------------------------------------------------------------------
template<bool IN16>
__global__ __launch_bounds__(256) void rmsnorm_h16(
    const void* __restrict__ xin, const float* __restrict__ w,
    f16* __restrict__ o)
{
    int tkn = blockIdx.x;
    int t = threadIdx.x;
    float f[4];
    if (IN16) {
        const f16* xp = (const f16*)xin;
        uint2 u = reinterpret_cast<const uint2*>(xp + (size_t)tkn * HIDDEN)[t];
        __half2 p0 = *reinterpret_cast<__half2*>(&u.x);
        __half2 p1 = *reinterpret_cast<__half2*>(&u.y);
        f[0] = __low2float(p0); f[1] = __high2float(p0);
        f[2] = __low2float(p1); f[3] = __high2float(p1);
    } else {
        float4 v = reinterpret_cast<const float4*>((const float*)xin + (size_t)tkn * HIDDEN)[t];
        f[0] = v.x; f[1] = v.y; f[2] = v.z; f[3] = v.w;
    }
    float s = f[0]*f[0] + f[1]*f[1] + f[2]*f[2] + f[3]*f[3];
    #pragma unroll
    for (int o2 = 16; o2 > 0; o2 >>= 1) s += __shfl_xor_sync(0xFFFFFFFFu, s, o2);
    __shared__ float ws[8];
    __shared__ float tot_sh;
    if ((t & 31) == 0) ws[t >> 5] = s;
    __syncthreads();
    if (t < 32) {
        float z = (t < 8) ? ws[t] : 0.0f;
        #pragma unroll
        for (int o2 = 4; o2 > 0; o2 >>= 1) z += __shfl_xor_sync(0xFFFFFFFFu, z, o2);
        if (t == 0) tot_sh = z;
    }
    __syncthreads();
    float r = rsqrtf(tot_sh * (1.0f / HIDDEN) + 1e-6f);
    float4 wv = reinterpret_cast<const float4*>(w)[t];
    size_t q = (size_t)tkn * (HIDDEN / 4) + t;
    reinterpret_cast<uint2*>(o)[q] = make_uint2(
        pack_h2(__float2half(f[0] * r * wv.x), __float2half(f[1] * r * wv.y)),
        pack_h2(__float2half(f[2] * r * wv.z), __float2half(f[3] * r * wv.w)));
}

// ---------------------------------------------------------------------------
// Single-B GEMM (CTA 128x128, 4 warps @ 64x64, 3-stage mbarrier ring)
// ---------------------------------------------------------------------------
#define EPI_NONE          0
#define EPI_BIAS_SIGMOID  2
#define EPI_RESADD_F32    3
#define EPI_RESADD_F16    4

template<int EPI>
__device__ __forceinline__ float epi_apply(float v,
                                           const float* __restrict__ auxf,
                                           const f16* __restrict__ auxh,
                                           size_t idx, int col)
{
    if (EPI == EPI_BIAS_SIGMOID) return fast_sig(v + __ldg(&auxf[col]));
    if (EPI == EPI_RESADD_F32)   return v + __ldg(&auxf[idx]);
    if (EPI == EPI_RESADD_F16)   return v + __half2float(__ldg(&auxh[idx]));
    return v;
}

#define STAGE_B   32768u
#define GEMM_SMEM (3 * 32768 + 64)

template<int EPI, bool OUT16>
__global__ __launch_bounds__(128, 2) void mma_gemm(
    const f16* __restrict__ A, const f16* __restrict__ B,
    float* __restrict__ Cf, f16* __restrict__ Ch,
    const float* __restrict__ auxf, const f16* __restrict__ auxh,
    int M, int K)
{
    extern __shared__ char smem[];
    const uint32_t sb = smem_u32(smem);
    const uint32_t mb = sb + 3u * STAGE_B;
    const int tid = threadIdx.x;
    const int lane = tid & 31;
    const int wid = tid >> 5;
    const int warp_m = wid >> 1;
    const int warp_n = wid & 1;
    const int rowBlock = blockIdx.y * 128;
    const int colBlock = blockIdx.x * 128;
    const int nch = K >> 6;

    const f16* gpA = A + (size_t)rowBlock * K;
    const f16* gpB = B + (size_t)colBlock * K;

    if (tid == 0) {
        #pragma unroll
        for (int s = 0; s < 3; s++) {
            MBAR_INIT(mb + s * 8, 128);
            MBAR_INIT(mb + 24 + s * 8, 4);
        }
    }
    __syncthreads();

    auto issue = [&](int c, int buf) {
        const int kb = c * 64;
        uint32_t st = sb + (uint32_t)buf * STAGE_B;
        #pragma unroll
        for (int i = 0; i < 8; i++) {
            int u = tid + i * 128;
            int r = u >> 3, cc = u & 7;
            cp16(st + r * 128 + ((cc ^ (r & 7)) << 4),
                 gpA + (size_t)r * K + kb + cc * 8);
        }
        #pragma unroll
        for (int i = 0; i < 8; i++) {
            int u = tid + i * 128;
            int r = u >> 3, cc = u & 7;
            cp16(st + 16384u + r * 128 + ((cc ^ (r & 7)) << 4),
                 gpB + (size_t)r * K + kb + cc * 8);
        }
    };

    float acc[4][8][4];
    #pragma unroll
    for (int i = 0; i < 4; i++)
        #pragma unroll
        for (int j = 0; j < 8; j++)
            #pragma unroll
            for (int k = 0; k < 4; k++) acc[i][j][k] = 0.0f;

    int pstage = 0, pphase = 1;
    int cstage = 0, cphase = 0;

    #pragma unroll
    for (int s = 0; s < 3; s++) {
        if (s < nch) {
            MBAR_WAIT(mb + 24 + pstage * 8, pphase);
            issue(s, pstage);
            CP_MBAR_ARRIVE(mb + pstage * 8);
            pstage++; if (pstage == 3) { pstage = 0; pphase ^= 1; }
        }
    }

    const int aRow0 = warp_m * 64 + (lane & 7) + ((lane >> 3) & 1) * 8;
    const int aKh   = (lane >> 4) & 1;
    const int bRow0 = warp_n * 64 + ((lane >> 4) & 1) * 8 + (lane & 7);
    const int bKh   = (lane >> 3) & 1;
    const int swz   = lane & 7;

    for (int c = 0; c < nch; c++) {
        int s = cstage;
        MBAR_WAIT(mb + s * 8, cphase);
        cstage++; if (cstage == 3) { cstage = 0; cphase ^= 1; }

        uint32_t st = sb + (uint32_t)s * STAGE_B;
        #pragma unroll
        for (int ks = 0; ks < 4; ks++) {
            uint32_t afr[4][4];
            #pragma unroll
            for (int mt = 0; mt < 4; mt++) {
                uint32_t roff = (uint32_t)(aRow0 + mt * 16) * 128
                              + (uint32_t)(((ks * 2 + aKh) ^ swz) << 4);
                ldsm4(afr[mt], st + roff);
            }
            uint32_t bfr[8][2];
            #pragma unroll
            for (int p = 0; p < 4; p++) {
                uint32_t roff = (uint32_t)(bRow0 + p * 16) * 128
                              + (uint32_t)(((ks * 2 + bKh) ^ swz) << 4);
                uint32_t t4[4];
                ldsm4(t4, st + 16384u + roff);
                bfr[2 * p][0] = t4[0]; bfr[2 * p][1] = t4[1];
                bfr[2 * p + 1][0] = t4[2]; bfr[2 * p + 1][1] = t4[3];
            }
            #pragma unroll
            for (int mt = 0; mt < 4; mt++)
                #pragma unroll
                for (int nt = 0; nt < 8; nt++)
                    mma_f16(acc[mt][nt], afr[mt], bfr[nt][0], bfr[nt][1]);
        }

        if (lane == 0) MBAR_ARRIVE(mb + 24 + s * 8);

        if (c + 3 < nch) {
            MBAR_WAIT(mb + 24 + pstage * 8, pphase);
            issue(c + 3, pstage);
            CP_MBAR_ARRIVE(mb + pstage * 8);
            pstage++; if (pstage == 3) { pstage = 0; pphase ^= 1; }
        }
    }

    #pragma unroll
    for (int mt = 0; mt < 4; mt++) {
        #pragma unroll
        for (int nt = 0; nt < 8; nt++) {
            int col = colBlock + warp_n * 64 + nt * 8 + (lane & 3) * 2;
            #pragma unroll
            for (int half = 0; half < 2; half++) {
                int row = rowBlock + warp_m * 64 + mt * 16 + (lane >> 2) + half * 8;
                size_t idx = (size_t)row * M + col;
                float f0 = epi_apply<EPI>(acc[mt][nt][half * 2 + 0], auxf, auxh, idx, col);
                float f1 = epi_apply<EPI>(acc[mt][nt][half * 2 + 1], auxf, auxh, idx + 1, col + 1);
                if (OUT16) {
                    *reinterpret_cast<uint32_t*>(Ch + idx) =
                        pack_h2(__float2half(f0), __float2half(f1));
                } else {
                    *reinterpret_cast<float2*>(Cf + idx) = make_float2(f0, f1);
                }
            }
        }
    }
}

// ---------------------------------------------------------------------------
// Dual-B GEMM: T1 = A@B1^T, T2 = A@B2^T on one A pass.
// FUSE_SILU=1: C1 = silu(T1)*T2        (MLP gate+up)
// FUSE_SILU=0: C1 = T1, C2 = sigmoid(T2) (w_in + w_gate)
// ---------------------------------------------------------------------------
template<int FUSE_SILU>
__global__ __launch_bounds__(128, 2) void mma_gemm_dual(
    const f16* __restrict__ A, const f16* __restrict__ B1,
    const f16* __restrict__ B2, f16* __restrict__ C1, f16* __restrict__ C2,
    int M, int K)
{
    extern __shared__ char smem[];
    const uint32_t sb = smem_u32(smem);
    const uint32_t mb = sb + 3u * STAGE_B;
    const int tid = threadIdx.x;
    const int lane = tid & 31;
    const int wid = tid >> 5;
    const int warp_m = wid >> 1;
    const int warp_n = wid & 1;
    const int rowBlock = blockIdx.y * 128;
    const int colBlock = blockIdx.x * 64;
    const int nch = K >> 6;

    const f16* gpA  = A  + (size_t)rowBlock * K;
    const f16* gpB1 = B1 + (size_t)colBlock * K;
    const f16* gpB2 = B2 + (size_t)colBlock * K;

    if (tid == 0) {
        #pragma unroll
        for (int s = 0; s < 3; s++) {
            MBAR_INIT(mb + s * 8, 128);
            MBAR_INIT(mb + 24 + s * 8, 4);
        }
    }
    __syncthreads();

    auto issue = [&](int c, int buf) {
        const int kb = c * 64;
        uint32_t st = sb + (uint32_t)buf * STAGE_B;
        #pragma unroll
        for (int i = 0; i < 8; i++) {
            int u = tid + i * 128;
            int r = u >> 3, cc = u & 7;
            cp16(st + r * 128 + ((cc ^ (r & 7)) << 4),
                 gpA + (size_t)r * K + kb + cc * 8);
        }
        #pragma unroll
        for (int i = 0; i < 4; i++) {
            int u = tid + i * 128;
            int r = u >> 3, cc = u & 7;
            cp16(st + 16384u + r * 128 + ((cc ^ (r & 7)) << 4),
                 gpB1 + (size_t)r * K + kb + cc * 8);
        }
        #pragma unroll
        for (int i = 0; i < 4; i++) {
            int u = tid + i * 128;
            int r = u >> 3, cc = u & 7;
            cp16(st + 24576u + r * 128 + ((cc ^ (r & 7)) << 4),
                 gpB2 + (size_t)r * K + kb + cc * 8);
        }
    };

    float acc1[4][4][4], acc2[4][4][4];
    #pragma unroll
    for (int i = 0; i < 4; i++)
        #pragma unroll
        for (int j = 0; j < 4; j++)
            #pragma unroll
            for (int k = 0; k < 4; k++) { acc1[i][j][k] = 0.0f; acc2[i][j][k] = 0.0f; }

    int pstage = 0, pphase = 1;
    int cstage = 0, cphase = 0;

    #pragma unroll
    for (int s = 0; s < 3; s++) {
        if (s < nch) {
            MBAR_WAIT(mb + 24 + pstage * 8, pphase);
            issue(s, pstage);
            CP_MBAR_ARRIVE(mb + pstage * 8);
            pstage++; if (pstage == 3) { pstage = 0; pphase ^= 1; }
        }
    }

    const int aRow0 = warp_m * 64 + (lane & 7) + ((lane >> 3) & 1) * 8;
    const int aKh   = (lane >> 4) & 1;
    const int bRow0 = warp_n * 32 + ((lane >> 4) & 1) * 8 + (lane & 7);
    const int bKh   = (lane >> 3) & 1;
    const int swz   = lane & 7;

    for (int c = 0; c < nch; c++) {
        int s = cstage;
        MBAR_WAIT(mb + s * 8, cphase);
        cstage++; if (cstage == 3) { cstage = 0; cphase ^= 1; }

        uint32_t st = sb + (uint32_t)s * STAGE_B;
        #pragma unroll
        for (int ks = 0; ks < 4; ks++) {
            uint32_t afr[4][4];
            #pragma unroll
            for (int mt = 0; mt < 4; mt++) {
                uint32_t roff = (uint32_t)(aRow0 + mt * 16) * 128
                              + (uint32_t)(((ks * 2 + aKh) ^ swz) << 4);
                ldsm4(afr[mt], st + roff);
            }
            uint32_t b1fr[4][2], b2fr[4][2];
            #pragma unroll
            for (int p = 0; p < 2; p++) {
                uint32_t roff = (uint32_t)(bRow0 + p * 16) * 128
                              + (uint32_t)(((ks * 2 + bKh) ^ swz) << 4);
                uint32_t t4[4];
                ldsm4(t4, st + 16384u + roff);
                b1fr[2 * p][0] = t4[0]; b1fr[2 * p][1] = t4[1];
                b1fr[2 * p + 1][0] = t4[2]; b1fr[2 * p + 1][1] = t4[3];
                ldsm4(t4, st + 24576u + roff);
                b2fr[2 * p][0] = t4[0]; b2fr[2 * p][1] = t4[1];
                b2fr[2 * p + 1][0] = t4[2]; b2fr[2 * p + 1][1] = t4[3];
            }
            #pragma unroll
            for (int mt = 0; mt < 4; mt++)
                #pragma unroll
                for (int nt = 0; nt < 4; nt++)
                    mma_f16(acc1[mt][nt], afr[mt], b1fr[nt][0], b1fr[nt][1]);
            #pragma unroll
            for (int mt = 0; mt < 4; mt++)
                #pragma unroll
                for (int nt = 0; nt < 4; nt++)
                    mma_f16(acc2[mt][nt], afr[mt], b2fr[nt][0], b2fr[nt][1]);
        }

        if (lane == 0) MBAR_ARRIVE(mb + 24 + s * 8);

        if (c + 3 < nch) {
            MBAR_WAIT(mb + 24 + pstage * 8, pphase);
            issue(c + 3, pstage);
            CP_MBAR_ARRIVE(mb + pstage * 8);
            pstage++; if (pstage == 3) { pstage = 0; pphase ^= 1; }
        }
    }

    #pragma unroll
    for (int mt = 0; mt < 4; mt++) {
        #pragma unroll
        for (int nt = 0; nt < 4; nt++) {
            int col = colBlock + warp_n * 32 + nt * 8 + (lane & 3) * 2;
            #pragma unroll
            for (int half = 0; half < 2; half++) {
                int row = rowBlock + warp_m * 64 + mt * 16 + (lane >> 2) + half * 8;
                size_t idx = (size_t)row * M + col;
                float t10 = acc1[mt][nt][half * 2 + 0], t20 = acc2[mt][nt][half * 2 + 0];
                float t11 = acc1[mt][nt][half * 2 + 1], t21 = acc2[mt][nt][half * 2 + 1];
                if (FUSE_SILU) {
                    float f0 = t10 * fast_sig(t10) * t20;
                    float f1 = t11 * fast_sig(t11) * t21;
                    *reinterpret_cast<uint32_t*>(C1 + idx) =
                        pack_h2(__float2half(f0), __float2half(f1));
                } else {
                    *reinterpret_cast<uint32_t*>(C1 + idx) =
                        pack_h2(__float2half(t10), __float2half(t11));
                    *reinterpret_cast<uint32_t*>(C2 + idx) =
                        pack_h2(__float2half(fast_sig(t20)), __float2half(fast_sig(t21)));
                }
            }
        }
    }
}

// ---------------------------------------------------------------------------
// Parallel Hawk scan, recompute style, h2-paired channels.
// Each thread scans TWO adjacent d-channels -> full 128B/warp coalescing.
// ---------------------------------------------------------------------------
__global__ __launch_bounds__(256) void scan_part1(
    const f16* __restrict__ xin, const f16* __restrict__ a,
    float* __restrict__ csum)
{
    int id = blockIdx.x * 256 + threadIdx.x;      // 0 .. NCHUNKS*NCHAN/2-1
    int chunk = id >> 12;                         // / 4096
    int chp2 = id & (NCHAN / 2 - 1);
    int b = chp2 >> 10;                           // / (DREC/2)
    int d = (chp2 & (DREC / 2 - 1)) * 2;
    size_t base = ((size_t)b * TLEN + (size_t)chunk * SCHUNK) * DREC + d;

    float h0 = 0.0f, h1 = 0.0f, A0 = 1.0f, A1 = 1.0f;
    #pragma unroll 4
    for (int t = 0; t < SCHUNK; t++) {
        size_t idx = base + (size_t)t * DREC;
        __half2 av = __ldg(reinterpret_cast<const __half2*>(a + idx));
        __half2 xv = __ldg(reinterpret_cast<const __half2*>(xin + idx));
        float a0 = __low2float(av), a1 = __high2float(av);
        float x0 = __low2float(xv), x1 = __high2float(xv);
        h0 = fmaf(a0, h0, sqrtf(fmaf(-a0, a0, 1.0f) + 1e-8f) * x0);
        h1 = fmaf(a1, h1, sqrtf(fmaf(-a1, a1, 1.0f) + 1e-8f) * x1);
        A0 *= a0; A1 *= a1;
    }
    int chp = b * DREC + d;
    *reinterpret_cast<float2*>(&csum[(size_t)chunk * NCHAN + chp]) = make_float2(A0, A1);
    *reinterpret_cast<float2*>(&csum[(size_t)NCHUNKS * NCHAN + (size_t)chunk * NCHAN + chp]) = make_float2(h0, h1);
}

__global__ __launch_bounds__(256) void scan_part2(
    const float* __restrict__ csum, float* __restrict__ carry)
{
    int chp = blockIdx.x * 256 + threadIdx.x;
    float h = 0.0f;
    #pragma unroll
    for (int c = 0; c < NCHUNKS; c++) {
        carry[(size_t)c * NCHAN + chp] = h;
        float Ac = __ldg(&csum[(size_t)c * NCHAN + chp]);
        float hc = __ldg(&csum[(size_t)NCHUNKS * NCHAN + (size_t)c * NCHAN + chp]);
        h = fmaf(Ac, h, hc);
    }
}

__global__ __launch_bounds__(256) void scan_part3(
    const f16* __restrict__ xin, const f16* __restrict__ a,
    const f16* __restrict__ gate, const float* __restrict__ carry,
    f16* __restrict__ y)
{
    int id = blockIdx.x * 256 + threadIdx.x;
    int chunk = id >> 12;
    int chp2 = id & (NCHAN / 2 - 1);
    int b = chp2 >> 10;
    int d = (chp2 & (DREC / 2 - 1)) * 2;
    size_t base = ((size_t)b * TLEN + (size_t)chunk * SCHUNK) * DREC + d;

    int chp = b * DREC + d;
    float2 cv = *reinterpret_cast<const float2*>(&carry[(size_t)chunk * NCHAN + chp]);
    float h0 = cv.x, h1 = cv.y;
    #pragma unroll 4
    for (int t = 0; t < SCHUNK; t++) {
        size_t idx = base + (size_t)t * DREC;
        __half2 av = __ldg(reinterpret_cast<const __half2*>(a + idx));
        __half2 xv = __ldg(reinterpret_cast<const __half2*>(xin + idx));
        __half2 gv = __ldg(reinterpret_cast<const __half2*>(gate + idx));
        float a0 = __low2float(av), a1 = __high2float(av);
        float x0 = __low2float(xv), x1 = __high2float(xv);
        h0 = fmaf(a0, h0, sqrtf(fmaf(-a0, a0, 1.0f) + 1e-8f) * x0);
        h1 = fmaf(a1, h1, sqrtf(fmaf(-a1, a1, 1.0f) + 1e-8f) * x1);
        *reinterpret_cast<uint32_t*>(y + idx) =
            pack_h2(__float2half(__low2float(gv) * h0),
                    __float2half(__high2float(gv) * h1));
    }
}

// ---------------------------------------------------------------------------
// Launch
// ---------------------------------------------------------------------------
#define SYM(p, s) cudaGetSymbolAddress((void**)&p, s)

extern "C" void kernel_launch(void* const* d_in, const int* in_sizes, int n_in,
                              void* d_out, int out_size)
{
    const float* x       = (const float*)d_in[0];
    const float* ln1_w   = (const float*)d_in[1];
    const float* ln2_w   = (const float*)d_in[2];
    const float* w_in    = (const float*)d_in[3];
    const float* w_gate  = (const float*)d_in[4];
    const float* a_param = (const float*)d_in[5];
    const float* w_a     = (const float*)d_in[6];
    const float* w_out   = (const float*)d_in[7];
    const float* w_mg    = (const float*)d_in[8];
    const float* w_mu    = (const float*)d_in[9];
    const float* w_md    = (const float*)d_in[10];
    float* out = (float*)d_out;

    f16 *hh, *h2h, *xinh, *gateh, *ah, *yh, *muh, *xresh;
    float *csum, *carry;
    f16 *wi, *wiT, *wg, *wa, *wcomb, *wo, *wmgp, *wmup, *wmdp;

    SYM(hh, g_h);     SYM(h2h, g_h2);
    SYM(xinh, g_xin); SYM(gateh, g_gate); SYM(ah, g_a);
    SYM(yh, g_y);     SYM(muh, g_mu);     SYM(xresh, g_xres);
    SYM(csum, g_csum); SYM(carry, g_carry);
    SYM(wi, g_wi);  SYM(wiT, g_wiT);  SYM(wg, g_wg);  SYM(wa, g_wa);
    SYM(wcomb, g_wcomb);  SYM(wo, g_wo);
    SYM(wmgp, g_wmg); SYM(wmup, g_wmu); SYM(wmdp, g_wmd);

    cudaFuncSetAttribute(mma_gemm<EPI_NONE, true>,          cudaFuncAttributeMaxDynamicSharedMemorySize, GEMM_SMEM);
    cudaFuncSetAttribute(mma_gemm<EPI_BIAS_SIGMOID, true>,  cudaFuncAttributeMaxDynamicSharedMemorySize, GEMM_SMEM);
    cudaFuncSetAttribute(mma_gemm<EPI_RESADD_F32, true>,    cudaFuncAttributeMaxDynamicSharedMemorySize, GEMM_SMEM);
    cudaFuncSetAttribute(mma_gemm<EPI_RESADD_F16, false>,   cudaFuncAttributeMaxDynamicSharedMemorySize, GEMM_SMEM);
    cudaFuncSetAttribute(mma_gemm_dual<0>,                  cudaFuncAttributeMaxDynamicSharedMemorySize, GEMM_SMEM);
    cudaFuncSetAttribute(mma_gemm_dual<1>,                  cudaFuncAttributeMaxDynamicSharedMemorySize, GEMM_SMEM);

    dim3 blk(256);
    dim3 gblk(128);
    const int GY = NTOK / 128;   // 128

    const int n_ih = DREC * HIDDEN / 4;   // 524288
    const int n_aa = DREC * DREC / 4;     // 1048576
    const int n_mh = INTER * HIDDEN / 4;  // 1048576

    // convert all 7 weights to fp16
    {
        int total = 3 * n_ih + n_aa + 3 * n_mh;
        conv7<<<(total + 255) / 256, blk>>>(
            w_in, wi, n_ih,
            w_gate, wg, n_ih,
            w_a, wa, n_aa,
            w_out, wo, n_ih,
            w_mg, wmgp, n_mh,
            w_mu, wmup, n_mh,
            w_md, wmdp, n_mh);
    }

    // wiT = wi^T
    transpose_h16<<<dim3(HIDDEN / 32, DREC / 32), blk>>>(wi, wiT, DREC, HIDDEN);

    // Wcomb = Wa @ Wi
    mma_gemm<EPI_NONE, true><<<dim3(HIDDEN / 128, DREC / 128), gblk, GEMM_SMEM>>>(
        wa, wiT, nullptr, wcomb, nullptr, nullptr, HIDDEN, DREC);

    // h = rmsnorm(x, ln1)
    rmsnorm_h16<false><<<NTOK, blk>>>(x, ln1_w, hh);

    // fused: xin = h@Wi^T, gate = sigmoid(h@Wg^T)
    mma_gemm_dual<0><<<dim3(DREC / 64, GY), gblk, GEMM_SMEM>>>(
        hh, wi, wg, xinh, gateh, DREC, HIDDEN);

    // a = sigmoid(a_param + h @ Wcomb^T)   (K=1024, composed)
    mma_gemm<EPI_BIAS_SIGMOID, true><<<dim3(DREC / 128, GY), gblk, GEMM_SMEM>>>(
        hh, wcomb, nullptr, ah, a_param, nullptr, DREC, HIDDEN);

    // scan (h2-paired)
    scan_part1<<<(NCHUNKS * NCHAN / 2) / 256, blk>>>(xinh, ah, csum);
    scan_part2<<<NCHAN / 256, blk>>>(csum, carry);
    scan_part3<<<(NCHUNKS * NCHAN / 2) / 256, blk>>>(xinh, ah, gateh, carry, yh);

    // xres = x + y @ w_out^T  (f16 out, f32 aux)
    mma_gemm<EPI_RESADD_F32, true><<<dim3(HIDDEN / 128, GY), gblk, GEMM_SMEM>>>(
        yh, wo, nullptr, xresh, x, nullptr, HIDDEN, DREC);

    // h2 = rmsnorm(xres, ln2)  (f16 in)
    rmsnorm_h16<true><<<NTOK, blk>>>(xresh, ln2_w, h2h);

    // fused MLP gate+up: mu = silu(h2@Wg^T) * (h2@Wu^T)
    mma_gemm_dual<1><<<dim3(INTER / 64, GY), gblk, GEMM_SMEM>>>(
        h2h, wmgp, wmup, muh, nullptr, INTER, HIDDEN);

    // out = xres + mu @ w_mlp_down^T  (f32 out, f16 aux)
    mma_gemm<EPI_RESADD_F16, false><<<dim3(HIDDEN / 128, GY), gblk, GEMM_SMEM>>>(
        muh, wmdp, out, nullptr, nullptr, xresh, HIDDEN, INTER);
}